// round 13
// baseline (speedup 1.0000x reference)
#include <cuda_runtime.h>
#include <cuda_bf16.h>
#include <cuda_fp16.h>
#include <math.h>
#include <stdint.h>

#define T_  64
#define B_  256
#define D_  512
#define H_  512

// ---------------- device scratch (allocation-free rule) ----------------
__device__ __half g_H1f[B_ * 4 * H_];          // fp16(H1), row = b*4 + gate
__device__ __half g_Bf[H_ * H_];               // fp16(pW2^T), [n][k]
__device__ __nv_bfloat16 g_Wxh[32 * D_];       // hi(Wx^T) [o][k] for xproj
__device__ __nv_bfloat16 g_Wxl[32 * D_];       // lo(Wx^T)
__device__ float g_bx[32];                     // gate bias vector
__device__ float g_Xproj[T_ * B_ * 32];        // x_t @ W + b, [t*B+b][g*8+q]
__device__ float g_Zpart[8 * B_ * 32];         // per-n-tile partial h-projections
__device__ float g_Wh2t[H_ * 32];              // W[D+col][g*8+q] as [col][32]
__device__ float2 g_ry[4 * 2 * 8];             // (cy,sy) per (g,l,q)
__device__ float2 g_pl2[4 * 2 * 32];           // lane-deferred RZ phase per (g,l,lane)
__device__ float2 g_pr2[4 * 2 * 8];            // reg-deferred RZ phase per (g,l,r)

// ---------------- PTX helpers ----------------
__device__ __forceinline__ uint32_t smem_u32(const void* p) {
    uint32_t a;
    asm("{ .reg .u64 t; cvta.to.shared.u64 t, %1; cvt.u32.u64 %0, t; }" : "=r"(a) : "l"(p));
    return a;
}
__device__ __forceinline__ void cp16cg(uint32_t dst, const void* src) {
    asm volatile("cp.async.cg.shared.global [%0], [%1], 16;" :: "r"(dst), "l"(src) : "memory");
}
#define CP_COMMIT() asm volatile("cp.async.commit_group;" ::: "memory")
template<int N> __device__ __forceinline__ void cp_wait() {
    asm volatile("cp.async.wait_group %0;" :: "n"(N) : "memory");
}
__device__ __forceinline__ void ldm4(uint32_t addr, uint32_t* r) {
    asm volatile("ldmatrix.sync.aligned.m8n8.x4.shared.b16 {%0,%1,%2,%3}, [%4];"
        : "=r"(r[0]), "=r"(r[1]), "=r"(r[2]), "=r"(r[3]) : "r"(addr));
}
__device__ __forceinline__ void mma_bf16(float* c, const uint32_t* a, uint32_t b0, uint32_t b1) {
    asm volatile(
        "mma.sync.aligned.m16n8k16.row.col.f32.bf16.bf16.f32 "
        "{%0,%1,%2,%3}, {%4,%5,%6,%7}, {%8,%9}, {%0,%1,%2,%3};"
        : "+f"(c[0]), "+f"(c[1]), "+f"(c[2]), "+f"(c[3])
        : "r"(a[0]), "r"(a[1]), "r"(a[2]), "r"(a[3]), "r"(b0), "r"(b1));
}
__device__ __forceinline__ void mma_f16(float* c, const uint32_t* a, uint32_t b0, uint32_t b1) {
    asm volatile(
        "mma.sync.aligned.m16n8k16.row.col.f32.f16.f16.f32 "
        "{%0,%1,%2,%3}, {%4,%5,%6,%7}, {%8,%9}, {%0,%1,%2,%3};"
        : "+f"(c[0]), "+f"(c[1]), "+f"(c[2]), "+f"(c[3])
        : "r"(a[0]), "r"(a[1]), "r"(a[2]), "r"(a[3]), "r"(b0), "r"(b1));
}
__device__ __forceinline__ float sigmoidf_(float x) { return 1.f / (1.f + expf(-x)); }

// cluster barrier (arrive has cluster-scope release; wait has acquire)
#define CL_ARRIVE() asm volatile("barrier.cluster.arrive.aligned;" ::: "memory")
#define CL_WAIT()   asm volatile("barrier.cluster.wait.aligned;" ::: "memory")

// ---------------- prep kernels ----------------
// pW2 (K,N) -> transposed single fp16 [n][k]
__global__ void bprep_kernel(const float* __restrict__ pW2) {
    int i = blockIdx.x * blockDim.x + threadIdx.x;
    int n = i >> 9, k = i & 511;
    g_Bf[i] = __float2half(pW2[k * H_ + n]);
}

__global__ void whprep_kernel(
    const float* __restrict__ Wf, const float* __restrict__ Wi,
    const float* __restrict__ Wu, const float* __restrict__ Wo,
    const float* __restrict__ bf, const float* __restrict__ bi,
    const float* __restrict__ bu, const float* __restrict__ bo)
{
    int i = blockIdx.x * blockDim.x + threadIdx.x;   // 0..16383
    {
        int col = i >> 5, o = i & 31, g = o >> 3, q = o & 7;
        const float* W = (g == 0) ? Wf : (g == 1) ? Wi : (g == 2) ? Wu : Wo;
        g_Wh2t[i] = W[(D_ + col) * 8 + q];
    }
    {
        int o = i >> 9, k = i & 511, g = o >> 3, q = o & 7;
        const float* W = (g == 0) ? Wf : (g == 1) ? Wi : (g == 2) ? Wu : Wo;
        float v = W[k * 8 + q];
        __nv_bfloat16 hi = __float2bfloat16(v);
        __nv_bfloat16 lo = __float2bfloat16(v - __bfloat162float(hi));
        g_Wxh[i] = hi; g_Wxl[i] = lo;
    }
    if (i < 32) {
        int g = i >> 3, q = i & 7;
        const float* bb = (g == 0) ? bf : (g == 1) ? bi : (g == 2) ? bu : bo;
        g_bx[i] = bb[q];
    }
}

__global__ void tabprep_kernel(
    const float* __restrict__ qpf, const float* __restrict__ qpi,
    const float* __restrict__ qpu, const float* __restrict__ qpo)
{
    int i = threadIdx.x;   // 0..255
    const float* qps[4] = {qpf, qpi, qpu, qpo};
    if (i < 64) {
        int g = i >> 4, l = (i >> 3) & 1, q = i & 7;
        const float* qp = qps[g];
        float th = qp[(l * 8 + q) * 3 + 0] * 0.5f;
        g_ry[i] = make_float2(cosf(th), sinf(th));
        int r = q;
        float prr = 1.f, pri = 0.f;
        #pragma unroll
        for (int qq = 5; qq < 8; qq++) {
            float tz = qp[(l * 8 + qq) * 3 + 1] * 0.5f;
            float cz = cosf(tz), sz = sinf(tz);
            float zn = ((r >> (7 - qq)) & 1) ? sz : -sz;
            float nr = prr * cz - pri * zn;
            float ni = prr * zn + pri * cz;
            prr = nr; pri = ni;
        }
        g_pr2[i] = make_float2(prr, pri);
    }
    {
        int g = i >> 6, l = (i >> 5) & 1, ln = i & 31;
        const float* qp = qps[g];
        float prr = 1.f, pri = 0.f;
        #pragma unroll
        for (int q = 0; q < 5; q++) {
            float tz = qp[(l * 8 + q) * 3 + 1] * 0.5f;
            float cz = cosf(tz), sz = sinf(tz);
            float zn = ((ln >> (4 - q)) & 1) ? sz : -sz;
            float nr = prr * cz - pri * zn;
            float ni = prr * zn + pri * cz;
            prr = nr; pri = ni;
        }
        g_pl2[i] = make_float2(prr, pri);
    }
}

// ---------------- xproj v4: HMMA GEMM, 256 threads, 8 warps ----------------
#define XROWB 1040u
#define XA_H 0u
#define XA_L 66560u
#define XB_H 133120u
#define XB_L 166400u
#define XP3_SMEM 199680

__global__ __launch_bounds__(256, 1) void xproj_kernel(const float* __restrict__ inputs)
{
    extern __shared__ __align__(16) char xsm[];
    uint32_t s0 = smem_u32(xsm);
    int tid = threadIdx.x, wid = tid >> 5, lane = tid & 31;
    int m0 = blockIdx.x * 64;

    #pragma unroll
    for (int j = 0; j < 8; j++) {               // B: 2048 16B units
        int u = tid + 256 * j;
        int row = u >> 6, ku = u & 63;
        uint32_t dst = (uint32_t)row * XROWB + (uint32_t)ku * 16u;
        cp16cg(s0 + XB_H + dst, g_Wxh + row * D_ + ku * 8);
        cp16cg(s0 + XB_L + dst, g_Wxl + row * D_ + ku * 8);
    }
    CP_COMMIT();

    #pragma unroll
    for (int j = 0; j < 32; j++) {              // A: 8192 float4 units
        int u = tid + 256 * j;
        int row = u >> 7, f4 = u & 127;
        float4 xv = *(const float4*)(inputs + (size_t)(m0 + row) * D_ + f4 * 4);
        __nv_bfloat16 h0 = __float2bfloat16(xv.x), h1 = __float2bfloat16(xv.y);
        __nv_bfloat16 h2 = __float2bfloat16(xv.z), h3 = __float2bfloat16(xv.w);
        __nv_bfloat16 l0 = __float2bfloat16(xv.x - __bfloat162float(h0));
        __nv_bfloat16 l1 = __float2bfloat16(xv.y - __bfloat162float(h1));
        __nv_bfloat16 l2 = __float2bfloat16(xv.z - __bfloat162float(h2));
        __nv_bfloat16 l3 = __float2bfloat16(xv.w - __bfloat162float(h3));
        uint2 ph, pl;
        ph.x = ((uint32_t)__bfloat16_as_ushort(h1) << 16) | __bfloat16_as_ushort(h0);
        ph.y = ((uint32_t)__bfloat16_as_ushort(h3) << 16) | __bfloat16_as_ushort(h2);
        pl.x = ((uint32_t)__bfloat16_as_ushort(l1) << 16) | __bfloat16_as_ushort(l0);
        pl.y = ((uint32_t)__bfloat16_as_ushort(l3) << 16) | __bfloat16_as_ushort(l2);
        uint32_t off = (uint32_t)row * XROWB + (uint32_t)f4 * 8u;
        *(uint2*)(xsm + XA_H + off) = ph;
        *(uint2*)(xsm + XA_L + off) = pl;
    }
    cp_wait<0>();
    __syncthreads();

    // warp: wm=(wid>>1)*16 rows, nh=wid&1 covers n cols [nh*16, nh*16+16)
    int wm = (wid >> 1) * 16, nh = wid & 1;
    float acc[2][4];
    #pragma unroll
    for (int j = 0; j < 2; j++)
        #pragma unroll
        for (int r = 0; r < 4; r++) acc[j][r] = 0.f;

    uint32_t aOff = (uint32_t)(wm + (lane & 15)) * XROWB + (uint32_t)((lane >> 4) << 4);
    uint32_t bOff = (uint32_t)(nh * 16 + (lane & 15)) * XROWB + (uint32_t)((lane >> 4) << 4);

    #pragma unroll 4
    for (int k16 = 0; k16 < 32; k16++) {
        uint32_t kb = (uint32_t)k16 * 32u;
        uint32_t ah[4], al[4], bh[4], bl[4];
        ldm4(s0 + XA_H + aOff + kb, ah);
        ldm4(s0 + XA_L + aOff + kb, al);
        ldm4(s0 + XB_H + bOff + kb, bh);
        ldm4(s0 + XB_L + bOff + kb, bl);
        #pragma unroll
        for (int j = 0; j < 2; j++) {
            mma_bf16(acc[j], ah, bh[j], bh[2 + j]);
            mma_bf16(acc[j], ah, bl[j], bl[2 + j]);
            mma_bf16(acc[j], al, bh[j], bh[2 + j]);
        }
    }

    int r0 = m0 + wm + (lane >> 2);
    #pragma unroll
    for (int j = 0; j < 2; j++) {
        int col = (nh * 2 + j) * 8 + (lane & 3) * 2;
        float b0 = g_bx[col], b1 = g_bx[col + 1];
        *(float2*)(g_Xproj + (size_t)r0 * 32 + col)       = make_float2(acc[j][0] + b0, acc[j][1] + b1);
        *(float2*)(g_Xproj + (size_t)(r0 + 8) * 32 + col) = make_float2(acc[j][2] + b0, acc[j][3] + b1);
    }
}

// ---------------- the persistent recurrence kernel (clustered) --------------
// smem: B resident fp16 single; A 8 fully-issued chunks; resident tables.
#define BROWB 1040u
#define PB    0u
#define PA    66560u
#define PABUF 9216u
#define PW1S  140288u
#define WHS   156672u
#define PB1S  164864u
#define PB2S  166912u
#define CS    167168u
#define HSOFF 171264u
#define SMEM_DYN 175360
#define SROWB 144u
#define EPAD 68

__global__ __launch_bounds__(256, 1) __cluster_dims__(8, 1, 1)
void qlstm_kernel(
    const float* __restrict__ pW1, const float* __restrict__ pb1,
    const float* __restrict__ pb2, float* __restrict__ out)
{
    extern __shared__ __align__(16) char dsm[];
    const unsigned FULL = 0xffffffffu;
    uint32_t s0 = smem_u32(dsm);
    int tid = threadIdx.x, wid = tid >> 5, lane = tid & 31;
    int bid = blockIdx.x;
    int nt = bid & 7, mt = bid >> 3;      // cluster = 8 consecutive blocks = one mt group
    int n0 = nt * 64, m0 = mt * 64;

    int sidx = bid * 8 + wid;
    int qb = sidx >> 2, qg = sidx & 3;

    // ---- stage resident smem (one-time) ----
    #pragma unroll
    for (int j = 0; j < 16; j++) {              // B tile (single fp16)
        int u = tid + 256 * j;
        int row = u >> 6, ku = u & 63;
        cp16cg(s0 + PB + (uint32_t)row * BROWB + (uint32_t)ku * 16u,
               g_Bf + (size_t)(n0 + row) * H_ + ku * 8);
    }
    #pragma unroll
    for (int j = 0; j < 4; j++) {               // pW1 (16KB)
        int u = tid + 256 * j;
        cp16cg(s0 + PW1S + (uint32_t)u * 16u, pW1 + u * 4);
    }
    #pragma unroll
    for (int j = 0; j < 2; j++) {               // Wh tile (8KB)
        int u = tid + 256 * j;
        cp16cg(s0 + WHS + (uint32_t)u * 16u, g_Wh2t + (size_t)n0 * 32 + u * 4);
    }
    if (tid < 128) cp16cg(s0 + PB1S + (uint32_t)tid * 16u, pb1 + tid * 4);
    if (tid < 16)  cp16cg(s0 + PB2S + (uint32_t)tid * 16u, pb2 + n0 + tid * 4);
    CP_COMMIT();

    float* cs = (float*)(dsm + CS);
    #pragma unroll
    for (int j = 0; j < 4; j++) cs[tid + 256 * j] = 0.f;
    if (tid < 64) {
        #pragma unroll
        for (int p = 0; p < 8; p++)
            __stcg(g_Zpart + p * (B_ * 32) + bid * 64 + tid, 0.f);
    }
    cp_wait<0>();
    CL_ARRIVE(); CL_WAIT();

    // ---- hoisted constants ----
    const __half* Af = g_H1f + (size_t)m0 * H_;
    int wm = (wid >> 1) * 16, wn = (wid & 1) * 32;
    uint32_t aOff = (uint32_t)(wm + (lane & 15)) * SROWB + (uint32_t)((lane >> 4) << 4);
    uint32_t bOff = (uint32_t)(wn + (lane & 15)) * BROWB + (uint32_t)((lane >> 4) << 4);
    int lrow = tid >> 3, lun = tid & 7;
    int lrow2 = (tid + 256) >> 3, lun2 = (tid + 256) & 7;
    uint32_t ld0 = (uint32_t)lrow * SROWB + (uint32_t)lun * 16u;
    uint32_t ld1 = (uint32_t)lrow2 * SROWB + (uint32_t)lun2 * 16u;

    const float2* ryp = g_ry + qg * 16;
    const float2* prp = g_pr2 + qg * 16;
    const float* pw1s = (const float*)(dsm + PW1S);
    const float* pb1s = (const float*)(dsm + PB1S);
    const float* pb2s = (const float*)(dsm + PB2S);
    const float* whs  = (const float*)(dsm + WHS);

    for (int t = 0; t < T_; t++) {
        // ================= Q phase =================
        {
            // prefetch Xproj operand BEFORE waiting on the G(t-1) barrier
            float xp = 0.f;
            if (lane < 8) xp = g_Xproj[((t * B_ + qb) * 4 + qg) * 8 + lane];
            if (t > 0) CL_WAIT();

            float a = 0.f;
            if (lane < 8) {
                float zacc = 0.f;
                const float* zp = g_Zpart + qb * 32 + qg * 8 + lane;
                #pragma unroll
                for (int p = 0; p < 8; p++) zacc += __ldcg(zp + p * (B_ * 32));
                a = zacc + xp;
            }
            float sv, cv;
            __sincosf(a * 0.5f, &sv, &cv);

            float re[8], im[8];
            #pragma unroll
            for (int r = 0; r < 8; r++) { re[r] = 0.f; im[r] = 0.f; }
            if (lane == 0) re[0] = 1.f;

            #pragma unroll
            for (int q = 0; q < 5; q++) {
                int d = 16 >> q;
                float c = __shfl_sync(FULL, cv, q);
                float s = __shfl_sync(FULL, sv, q);
                #pragma unroll
                for (int r = 0; r < 8; r++) {
                    float pr = __shfl_xor_sync(FULL, re[r], d);
                    float pi = __shfl_xor_sync(FULL, im[r], d);
                    re[r] = c * re[r] + s * pi;
                    im[r] = c * im[r] - s * pr;
                }
            }
            #pragma unroll
            for (int q = 5; q < 8; q++) {
                int str = 1 << (7 - q);
                float c = __shfl_sync(FULL, cv, q);
                float s = __shfl_sync(FULL, sv, q);
                #pragma unroll
                for (int a0 = 0; a0 < 8; a0++) {
                    if (a0 & str) continue;
                    int b0 = a0 | str;
                    float tr0 = re[a0], ti0 = im[a0], tr1 = re[b0], ti1 = im[b0];
                    re[a0] = c * tr0 + s * ti1;
                    im[a0] = c * ti0 - s * tr1;
                    re[b0] = c * tr1 + s * ti0;
                    im[b0] = c * ti1 - s * tr0;
                }
            }

            #pragma unroll
            for (int l = 0; l < 2; l++) {
                #pragma unroll
                for (int q = 0; q < 5; q++) {
                    float2 ys = ryp[l * 8 + q];
                    int d = 16 >> q;
                    int hi = (lane >> (4 - q)) & 1;
                    float sgn = hi ? ys.y : -ys.y;
                    #pragma unroll
                    for (int r = 0; r < 8; r++) {
                        float pr = __shfl_xor_sync(FULL, re[r], d);
                        float pi = __shfl_xor_sync(FULL, im[r], d);
                        re[r] = ys.x * re[r] + sgn * pr;
                        im[r] = ys.x * im[r] + sgn * pi;
                    }
                }
                #pragma unroll
                for (int q = 5; q < 8; q++) {
                    float2 ys = ryp[l * 8 + q];
                    int str = 1 << (7 - q);
                    #pragma unroll
                    for (int a0 = 0; a0 < 8; a0++) {
                        if (a0 & str) continue;
                        int b0 = a0 | str;
                        float tr0 = re[a0], ti0 = im[a0], tr1 = re[b0], ti1 = im[b0];
                        re[a0] = ys.x * tr0 - ys.y * tr1;
                        im[a0] = ys.x * ti0 - ys.y * ti1;
                        re[b0] = ys.y * tr0 + ys.x * tr1;
                        im[b0] = ys.y * ti0 + ys.x * ti1;
                    }
                }
                if (l == 0) {
                    float2 pl = g_pl2[(qg * 2 + l) * 32 + lane];
                    #pragma unroll
                    for (int r = 0; r < 8; r++) {
                        float nr = pl.x * re[r] - pl.y * im[r];
                        im[r] = pl.x * im[r] + pl.y * re[r];
                        re[r] = nr;
                    }
                    #pragma unroll
                    for (int r = 0; r < 8; r++) {
                        float2 pq = prp[l * 8 + r];
                        float nr = pq.x * re[r] - pq.y * im[r];
                        im[r] = pq.x * im[r] + pq.y * re[r];
                        re[r] = nr;
                    }
                }
                #pragma unroll
                for (int ct = 0; ct < 4; ct++) {
                    int d = 8 >> ct, cb = 4 - ct;
                    int cbit = (lane >> cb) & 1;
                    #pragma unroll
                    for (int r = 0; r < 8; r++) {
                        float pr = __shfl_xor_sync(FULL, re[r], d);
                        float pi = __shfl_xor_sync(FULL, im[r], d);
                        re[r] = cbit ? pr : re[r];
                        im[r] = cbit ? pi : im[r];
                    }
                }
                {
                    int cbit = lane & 1;
                    #pragma unroll
                    for (int r = 0; r < 4; r++) {
                        float t1 = re[r], t2 = re[r + 4];
                        re[r]     = cbit ? t2 : t1;
                        re[r + 4] = cbit ? t1 : t2;
                        t1 = im[r]; t2 = im[r + 4];
                        im[r]     = cbit ? t2 : t1;
                        im[r + 4] = cbit ? t1 : t2;
                    }
                }
                {
                    float tt;
                    tt = re[4]; re[4] = re[6]; re[6] = tt;
                    tt = re[5]; re[5] = re[7]; re[7] = tt;
                    tt = im[4]; im[4] = im[6]; im[6] = tt;
                    tt = im[5]; im[5] = im[7]; im[7] = tt;
                }
                {
                    float tt;
                    tt = re[2]; re[2] = re[3]; re[3] = tt;
                    tt = re[6]; re[6] = re[7]; re[7] = tt;
                    tt = im[2]; im[2] = im[3]; im[3] = tt;
                    tt = im[6]; im[6] = im[7]; im[7] = tt;
                }
            }

            float p0 = re[0]*re[0]+im[0]*im[0], p1 = re[1]*re[1]+im[1]*im[1];
            float p2 = re[2]*re[2]+im[2]*im[2], p3 = re[3]*re[3]+im[3]*im[3];
            float p4 = re[4]*re[4]+im[4]*im[4], p5 = re[5]*re[5]+im[5]*im[5];
            float p6 = re[6]*re[6]+im[6]*im[6], p7 = re[7]*re[7]+im[7]*im[7];
            float S = p0+p1+p2+p3+p4+p5+p6+p7;
            float z[8];
            #pragma unroll
            for (int q = 0; q < 5; q++)
                z[q] = ((lane >> (4 - q)) & 1) ? -S : S;
            z[5] = (p0+p1+p2+p3) - (p4+p5+p6+p7);
            z[6] = (p0+p1+p4+p5) - (p2+p3+p6+p7);
            z[7] = (p0+p2+p4+p6) - (p1+p3+p5+p7);
            #pragma unroll
            for (int q = 0; q < 8; q++) {
                #pragma unroll
                for (int o = 16; o; o >>= 1) z[q] += __shfl_xor_sync(FULL, z[q], o);
            }

            int row = qb * 4 + qg;
            #pragma unroll
            for (int j = 0; j < 16; j++) {
                int col = j * 32 + lane;
                float a2 = pb1s[col];
                #pragma unroll
                for (int q = 0; q < 8; q++) a2 += z[q] * pw1s[q * H_ + col];
                a2 = fmaxf(a2, 0.f);
                g_H1f[row * H_ + col] = __float2half(a2);
            }
        }
        CL_ARRIVE(); CL_WAIT();   // Q -> G (peers' H1 visible)

        // ================= G phase: GEMM + LSTM + h-projection =================
        {
            float* outt = out + (size_t)t * (B_ * H_);
            // issue all 8 A-chunk loads as separate groups
            #pragma unroll
            for (int c = 0; c < 8; c++) {
                uint32_t sb = s0 + PA + c * PABUF;
                int kb = c * 64;
                cp16cg(sb + ld0, Af + (size_t)lrow * H_ + kb + lun * 8);
                cp16cg(sb + ld1, Af + (size_t)lrow2 * H_ + kb + lun2 * 8);
                CP_COMMIT();
            }
            float acc[4][4];
            #pragma unroll
            for (int j = 0; j < 4; j++)
                #pragma unroll
                for (int r = 0; r < 4; r++) acc[j][r] = 0.f;

            #define GSTEP(CC, NW) { \
                cp_wait<NW>(); \
                __syncthreads(); \
                uint32_t abuf = s0 + PA + (CC) * PABUF; \
                uint32_t bko = (uint32_t)(CC) * 128u; \
                _Pragma("unroll") \
                for (int kk = 0; kk < 4; kk++) { \
                    uint32_t kb2 = kk * 32; \
                    uint32_t af[4], bf2[2][4]; \
                    ldm4(abuf + aOff + kb2, af); \
                    ldm4(s0 + PB + bOff + bko + kb2, bf2[0]); \
                    ldm4(s0 + PB + bOff + 16 * BROWB + bko + kb2, bf2[1]); \
                    _Pragma("unroll") \
                    for (int j = 0; j < 4; j++) { \
                        int p = j >> 1, sb2 = j & 1; \
                        mma_f16(acc[j], af, bf2[p][sb2], bf2[p][2 + sb2]); \
                    } \
                } }
            GSTEP(0, 7) GSTEP(1, 6) GSTEP(2, 5) GSTEP(3, 4)
            GSTEP(4, 3) GSTEP(5, 2) GSTEP(6, 1) GSTEP(7, 0)
            #undef GSTEP
            __syncthreads();   // all A buffers consumed before aliasing as sp

            // stage preact (aliases A chunk buffers 0/1)
            float* sp = (float*)(dsm + PA);
            int r0 = wm + (lane >> 2);
            #pragma unroll
            for (int j = 0; j < 4; j++) {
                int cc = wn + j * 8 + (lane & 3) * 2;
                sp[r0 * EPAD + cc]           = acc[j][0];
                sp[r0 * EPAD + cc + 1]       = acc[j][1];
                sp[(r0 + 8) * EPAD + cc]     = acc[j][2];
                sp[(r0 + 8) * EPAD + cc + 1] = acc[j][3];
            }
            __syncthreads();

            float* hs = (float*)(dsm + HSOFF);
            bool last = (t == T_ - 1);
            #pragma unroll
            for (int jj = 0; jj < 4; jj++) {
                int e = tid + 256 * jj;
                int bi = e >> 6, col = e & 63;
                float bias = pb2s[col];
                float fv = sigmoidf_(sp[(bi * 4 + 0) * EPAD + col] + bias);
                float iv = sigmoidf_(sp[(bi * 4 + 1) * EPAD + col] + bias);
                float uv = tanhf   (sp[(bi * 4 + 2) * EPAD + col] + bias);
                float ov = sigmoidf_(sp[(bi * 4 + 3) * EPAD + col] + bias);
                float cc2 = fv * cs[e] + iv * uv;
                float hh2 = ov * tanhf(cc2);
                cs[e] = cc2;
                int batch = mt * 16 + bi;
                int idx = batch * H_ + n0 + col;
                outt[idx] = hh2;
                hs[bi * 64 + col] = hh2;
                if (last) {
                    out[(size_t)T_ * B_ * H_ + idx] = hh2;
                    out[(size_t)T_ * B_ * H_ + B_ * H_ + idx] = cc2;
                }
            }
            __syncthreads();

            #pragma unroll
            for (int jj = 0; jj < 2; jj++) {
                int idx2 = tid + 256 * jj;
                int bi = idx2 >> 5, o = idx2 & 31;
                const float* hh = hs + bi * 64;
                const float* wr = whs + o;
                float sacc = 0.f;
                #pragma unroll 16
                for (int c2 = 0; c2 < 64; c2++) sacc += hh[c2] * wr[c2 * 32];
                __stcg(g_Zpart + nt * (B_ * 32) + (mt * 16 + bi) * 32 + o, sacc);
            }
        }
        if (t < T_ - 1) CL_ARRIVE();   // matching CL_WAIT at top of next Q phase
    }
}

// ---------------- host ----------------
extern "C" void kernel_launch(void* const* d_in, const int* in_sizes, int n_in,
                              void* d_out, int out_size) {
    const float* inputs = (const float*)d_in[0];
    const float* qpf = (const float*)d_in[1];
    const float* qpi = (const float*)d_in[2];
    const float* qpu = (const float*)d_in[3];
    const float* qpo = (const float*)d_in[4];
    const float* Wf  = (const float*)d_in[5];
    const float* bf  = (const float*)d_in[6];
    const float* Wi  = (const float*)d_in[7];
    const float* bi  = (const float*)d_in[8];
    const float* Wu  = (const float*)d_in[9];
    const float* bu  = (const float*)d_in[10];
    const float* Wo  = (const float*)d_in[11];
    const float* bo  = (const float*)d_in[12];
    const float* pW1 = (const float*)d_in[13];
    const float* pb1 = (const float*)d_in[14];
    const float* pW2 = (const float*)d_in[15];
    const float* pb2 = (const float*)d_in[16];
    float* out = (float*)d_out;

    cudaFuncSetAttribute(qlstm_kernel, cudaFuncAttributeMaxDynamicSharedMemorySize, SMEM_DYN);
    cudaFuncSetAttribute(xproj_kernel, cudaFuncAttributeMaxDynamicSharedMemorySize, XP3_SMEM);

    bprep_kernel<<<(H_ * H_) / 256, 256>>>(pW2);
    whprep_kernel<<<(H_ * 32) / 256, 256>>>(Wf, Wi, Wu, Wo, bf, bi, bu, bo);
    tabprep_kernel<<<1, 256>>>(qpf, qpi, qpu, qpo);
    xproj_kernel<<<(T_ * B_) / 64, 256, XP3_SMEM>>>(inputs);
    qlstm_kernel<<<128, 256, SMEM_DYN>>>(pW1, pb1, pb2, out);
}

// round 14
// speedup vs baseline: 1.6173x; 1.6173x over previous
#include <cuda_runtime.h>
#include <cuda_bf16.h>
#include <cuda_fp16.h>
#include <math.h>
#include <stdint.h>

#define T_  64
#define B_  256
#define D_  512
#define H_  512

// ---------------- device scratch (allocation-free rule) ----------------
__device__ __half g_H1f[B_ * 4 * H_];          // fp16(H1), row = b*4 + gate
__device__ __half g_Bf[H_ * H_];               // fp16(pW2^T), [n][k]
__device__ __nv_bfloat16 g_Wxh[32 * D_];       // hi(Wx^T) [o][k] for xproj
__device__ __nv_bfloat16 g_Wxl[32 * D_];       // lo(Wx^T)
__device__ float g_bx[32];                     // gate bias vector
__device__ float g_Xproj[T_ * B_ * 32];        // x_t @ W + b, [t*B+b][g*8+q]
__device__ float g_Zpart[8 * B_ * 32];         // per-n-tile partial h-projections
__device__ float g_Wh2t[H_ * 32];              // W[D+col][g*8+q] as [col][32]
__device__ float2 g_ry[4 * 2 * 8];             // (cy,sy) per (g,l,q)
__device__ float2 g_pl2[4 * 2 * 32];           // lane-deferred RZ phase per (g,l,lane)
__device__ float2 g_pr2[4 * 2 * 8];            // reg-deferred RZ phase per (g,l,r)
__device__ int g_gcnt[16 * 32];                // padded: one 128B line per group
__device__ volatile int g_ggen[16 * 32];

// ---------------- PTX helpers ----------------
__device__ __forceinline__ uint32_t smem_u32(const void* p) {
    uint32_t a;
    asm("{ .reg .u64 t; cvta.to.shared.u64 t, %1; cvt.u32.u64 %0, t; }" : "=r"(a) : "l"(p));
    return a;
}
__device__ __forceinline__ void cp16cg(uint32_t dst, const void* src) {
    asm volatile("cp.async.cg.shared.global [%0], [%1], 16;" :: "r"(dst), "l"(src) : "memory");
}
#define CP_COMMIT() asm volatile("cp.async.commit_group;" ::: "memory")
template<int N> __device__ __forceinline__ void cp_wait() {
    asm volatile("cp.async.wait_group %0;" :: "n"(N) : "memory");
}
__device__ __forceinline__ void ldm4(uint32_t addr, uint32_t* r) {
    asm volatile("ldmatrix.sync.aligned.m8n8.x4.shared.b16 {%0,%1,%2,%3}, [%4];"
        : "=r"(r[0]), "=r"(r[1]), "=r"(r[2]), "=r"(r[3]) : "r"(addr));
}
__device__ __forceinline__ void mma_bf16(float* c, const uint32_t* a, uint32_t b0, uint32_t b1) {
    asm volatile(
        "mma.sync.aligned.m16n8k16.row.col.f32.bf16.bf16.f32 "
        "{%0,%1,%2,%3}, {%4,%5,%6,%7}, {%8,%9}, {%0,%1,%2,%3};"
        : "+f"(c[0]), "+f"(c[1]), "+f"(c[2]), "+f"(c[3])
        : "r"(a[0]), "r"(a[1]), "r"(a[2]), "r"(a[3]), "r"(b0), "r"(b1));
}
__device__ __forceinline__ void mma_f16(float* c, const uint32_t* a, uint32_t b0, uint32_t b1) {
    asm volatile(
        "mma.sync.aligned.m16n8k16.row.col.f32.f16.f16.f32 "
        "{%0,%1,%2,%3}, {%4,%5,%6,%7}, {%8,%9}, {%0,%1,%2,%3};"
        : "+f"(c[0]), "+f"(c[1]), "+f"(c[2]), "+f"(c[3])
        : "r"(a[0]), "r"(a[1]), "r"(a[2]), "r"(a[3]), "r"(b0), "r"(b1));
}
__device__ __forceinline__ float sigmoidf_(float x) { return 1.f / (1.f + expf(-x)); }

// ---------------- group barrier: 8 blocks (one m-tile group), padded lines ---
__device__ __forceinline__ void groupbar(int grp) {
    __syncthreads();
    if (threadIdx.x == 0) {
        __threadfence();
        int gen = g_ggen[grp * 32];
        if (atomicAdd(&g_gcnt[grp * 32], 1) == 7) {
            g_gcnt[grp * 32] = 0;
            __threadfence();
            g_ggen[grp * 32] = gen + 1;
        } else {
            while (g_ggen[grp * 32] == gen) __nanosleep(20);
        }
    }
    __syncthreads();
}

// ---------------- prep kernels ----------------
// pW2 (K,N) -> transposed single fp16 [n][k]
__global__ void bprep_kernel(const float* __restrict__ pW2) {
    int i = blockIdx.x * blockDim.x + threadIdx.x;
    int n = i >> 9, k = i & 511;
    g_Bf[i] = __float2half(pW2[k * H_ + n]);
}

__global__ void whprep_kernel(
    const float* __restrict__ Wf, const float* __restrict__ Wi,
    const float* __restrict__ Wu, const float* __restrict__ Wo,
    const float* __restrict__ bf, const float* __restrict__ bi,
    const float* __restrict__ bu, const float* __restrict__ bo)
{
    int i = blockIdx.x * blockDim.x + threadIdx.x;   // 0..16383
    {
        int col = i >> 5, o = i & 31, g = o >> 3, q = o & 7;
        const float* W = (g == 0) ? Wf : (g == 1) ? Wi : (g == 2) ? Wu : Wo;
        g_Wh2t[i] = W[(D_ + col) * 8 + q];
    }
    {
        int o = i >> 9, k = i & 511, g = o >> 3, q = o & 7;
        const float* W = (g == 0) ? Wf : (g == 1) ? Wi : (g == 2) ? Wu : Wo;
        float v = W[k * 8 + q];
        __nv_bfloat16 hi = __float2bfloat16(v);
        __nv_bfloat16 lo = __float2bfloat16(v - __bfloat162float(hi));
        g_Wxh[i] = hi; g_Wxl[i] = lo;
    }
    if (i < 32) {
        int g = i >> 3, q = i & 7;
        const float* bb = (g == 0) ? bf : (g == 1) ? bi : (g == 2) ? bu : bo;
        g_bx[i] = bb[q];
    }
}

__global__ void tabprep_kernel(
    const float* __restrict__ qpf, const float* __restrict__ qpi,
    const float* __restrict__ qpu, const float* __restrict__ qpo)
{
    int i = threadIdx.x;   // 0..255
    const float* qps[4] = {qpf, qpi, qpu, qpo};
    if (i < 64) {
        int g = i >> 4, l = (i >> 3) & 1, q = i & 7;
        const float* qp = qps[g];
        float th = qp[(l * 8 + q) * 3 + 0] * 0.5f;
        g_ry[i] = make_float2(cosf(th), sinf(th));
        int r = q;
        float prr = 1.f, pri = 0.f;
        #pragma unroll
        for (int qq = 5; qq < 8; qq++) {
            float tz = qp[(l * 8 + qq) * 3 + 1] * 0.5f;
            float cz = cosf(tz), sz = sinf(tz);
            float zn = ((r >> (7 - qq)) & 1) ? sz : -sz;
            float nr = prr * cz - pri * zn;
            float ni = prr * zn + pri * cz;
            prr = nr; pri = ni;
        }
        g_pr2[i] = make_float2(prr, pri);
    }
    {
        int g = i >> 6, l = (i >> 5) & 1, ln = i & 31;
        const float* qp = qps[g];
        float prr = 1.f, pri = 0.f;
        #pragma unroll
        for (int q = 0; q < 5; q++) {
            float tz = qp[(l * 8 + q) * 3 + 1] * 0.5f;
            float cz = cosf(tz), sz = sinf(tz);
            float zn = ((ln >> (4 - q)) & 1) ? sz : -sz;
            float nr = prr * cz - pri * zn;
            float ni = prr * zn + pri * cz;
            prr = nr; pri = ni;
        }
        g_pl2[i] = make_float2(prr, pri);
    }
}

// ---------------- xproj v4: HMMA GEMM, 256 threads, 8 warps ----------------
#define XROWB 1040u
#define XA_H 0u
#define XA_L 66560u
#define XB_H 133120u
#define XB_L 166400u
#define XP3_SMEM 199680

__global__ __launch_bounds__(256, 1) void xproj_kernel(const float* __restrict__ inputs)
{
    extern __shared__ __align__(16) char xsm[];
    uint32_t s0 = smem_u32(xsm);
    int tid = threadIdx.x, wid = tid >> 5, lane = tid & 31;
    int m0 = blockIdx.x * 64;

    #pragma unroll
    for (int j = 0; j < 8; j++) {               // B: 2048 16B units
        int u = tid + 256 * j;
        int row = u >> 6, ku = u & 63;
        uint32_t dst = (uint32_t)row * XROWB + (uint32_t)ku * 16u;
        cp16cg(s0 + XB_H + dst, g_Wxh + row * D_ + ku * 8);
        cp16cg(s0 + XB_L + dst, g_Wxl + row * D_ + ku * 8);
    }
    CP_COMMIT();

    #pragma unroll
    for (int j = 0; j < 32; j++) {              // A: 8192 float4 units
        int u = tid + 256 * j;
        int row = u >> 7, f4 = u & 127;
        float4 xv = *(const float4*)(inputs + (size_t)(m0 + row) * D_ + f4 * 4);
        __nv_bfloat16 h0 = __float2bfloat16(xv.x), h1 = __float2bfloat16(xv.y);
        __nv_bfloat16 h2 = __float2bfloat16(xv.z), h3 = __float2bfloat16(xv.w);
        __nv_bfloat16 l0 = __float2bfloat16(xv.x - __bfloat162float(h0));
        __nv_bfloat16 l1 = __float2bfloat16(xv.y - __bfloat162float(h1));
        __nv_bfloat16 l2 = __float2bfloat16(xv.z - __bfloat162float(h2));
        __nv_bfloat16 l3 = __float2bfloat16(xv.w - __bfloat162float(h3));
        uint2 ph, pl;
        ph.x = ((uint32_t)__bfloat16_as_ushort(h1) << 16) | __bfloat16_as_ushort(h0);
        ph.y = ((uint32_t)__bfloat16_as_ushort(h3) << 16) | __bfloat16_as_ushort(h2);
        pl.x = ((uint32_t)__bfloat16_as_ushort(l1) << 16) | __bfloat16_as_ushort(l0);
        pl.y = ((uint32_t)__bfloat16_as_ushort(l3) << 16) | __bfloat16_as_ushort(l2);
        uint32_t off = (uint32_t)row * XROWB + (uint32_t)f4 * 8u;
        *(uint2*)(xsm + XA_H + off) = ph;
        *(uint2*)(xsm + XA_L + off) = pl;
    }
    cp_wait<0>();
    __syncthreads();

    // warp: wm=(wid>>1)*16 rows, nh=wid&1 covers n cols [nh*16, nh*16+16)
    int wm = (wid >> 1) * 16, nh = wid & 1;
    float acc[2][4];
    #pragma unroll
    for (int j = 0; j < 2; j++)
        #pragma unroll
        for (int r = 0; r < 4; r++) acc[j][r] = 0.f;

    uint32_t aOff = (uint32_t)(wm + (lane & 15)) * XROWB + (uint32_t)((lane >> 4) << 4);
    uint32_t bOff = (uint32_t)(nh * 16 + (lane & 15)) * XROWB + (uint32_t)((lane >> 4) << 4);

    #pragma unroll 4
    for (int k16 = 0; k16 < 32; k16++) {
        uint32_t kb = (uint32_t)k16 * 32u;
        uint32_t ah[4], al[4], bh[4], bl[4];
        ldm4(s0 + XA_H + aOff + kb, ah);
        ldm4(s0 + XA_L + aOff + kb, al);
        ldm4(s0 + XB_H + bOff + kb, bh);
        ldm4(s0 + XB_L + bOff + kb, bl);
        #pragma unroll
        for (int j = 0; j < 2; j++) {
            mma_bf16(acc[j], ah, bh[j], bh[2 + j]);
            mma_bf16(acc[j], ah, bl[j], bl[2 + j]);
            mma_bf16(acc[j], al, bh[j], bh[2 + j]);
        }
    }

    int r0 = m0 + wm + (lane >> 2);
    #pragma unroll
    for (int j = 0; j < 2; j++) {
        int col = (nh * 2 + j) * 8 + (lane & 3) * 2;
        float b0 = g_bx[col], b1 = g_bx[col + 1];
        *(float2*)(g_Xproj + (size_t)r0 * 32 + col)       = make_float2(acc[j][0] + b0, acc[j][1] + b1);
        *(float2*)(g_Xproj + (size_t)(r0 + 8) * 32 + col) = make_float2(acc[j][2] + b0, acc[j][3] + b1);
    }
}

// ---------------- the persistent recurrence kernel ----------------
// smem: B resident fp16 single; A 8 fully-issued chunks; resident tables.
#define BROWB 1040u
#define PB    0u
#define PA    66560u
#define PABUF 9216u
#define PW1S  140288u
#define WHS   156672u
#define PB1S  164864u
#define PB2S  166912u
#define CS    167168u
#define HSOFF 171264u
#define SMEM_DYN 175360
#define SROWB 144u
#define EPAD 68

__global__ __launch_bounds__(256, 1) void qlstm_kernel(
    const float* __restrict__ pW1, const float* __restrict__ pb1,
    const float* __restrict__ pb2, float* __restrict__ out)
{
    extern __shared__ __align__(16) char dsm[];
    const unsigned FULL = 0xffffffffu;
    uint32_t s0 = smem_u32(dsm);
    int tid = threadIdx.x, wid = tid >> 5, lane = tid & 31;
    int bid = blockIdx.x;
    int nt = bid & 7, mt = bid >> 3;
    int grp = mt;
    int n0 = nt * 64, m0 = mt * 64;

    int sidx = bid * 8 + wid;
    int qb = sidx >> 2, qg = sidx & 3;

    // ---- stage resident smem (one-time) ----
    #pragma unroll
    for (int j = 0; j < 16; j++) {              // B tile (single fp16)
        int u = tid + 256 * j;                  // 4096 16B units
        int row = u >> 6, ku = u & 63;
        cp16cg(s0 + PB + (uint32_t)row * BROWB + (uint32_t)ku * 16u,
               g_Bf + (size_t)(n0 + row) * H_ + ku * 8);
    }
    #pragma unroll
    for (int j = 0; j < 4; j++) {               // pW1 (16KB)
        int u = tid + 256 * j;
        cp16cg(s0 + PW1S + (uint32_t)u * 16u, pW1 + u * 4);
    }
    #pragma unroll
    for (int j = 0; j < 2; j++) {               // Wh tile (8KB)
        int u = tid + 256 * j;
        cp16cg(s0 + WHS + (uint32_t)u * 16u, g_Wh2t + (size_t)n0 * 32 + u * 4);
    }
    if (tid < 128) cp16cg(s0 + PB1S + (uint32_t)tid * 16u, pb1 + tid * 4);
    if (tid < 16)  cp16cg(s0 + PB2S + (uint32_t)tid * 16u, pb2 + n0 + tid * 4);
    CP_COMMIT();

    float* cs = (float*)(dsm + CS);
    #pragma unroll
    for (int j = 0; j < 4; j++) cs[tid + 256 * j] = 0.f;
    if (tid < 64) {
        #pragma unroll
        for (int p = 0; p < 8; p++)
            __stcg(g_Zpart + p * (B_ * 32) + bid * 64 + tid, 0.f);
    }
    cp_wait<0>();
    groupbar(grp);

    // ---- hoisted constants ----
    const __half* Af = g_H1f + (size_t)m0 * H_;
    int wm = (wid >> 1) * 16, wn = (wid & 1) * 32;
    uint32_t aOff = (uint32_t)(wm + (lane & 15)) * SROWB + (uint32_t)((lane >> 4) << 4);
    uint32_t bOff = (uint32_t)(wn + (lane & 15)) * BROWB + (uint32_t)((lane >> 4) << 4);
    int lrow = tid >> 3, lun = tid & 7;
    int lrow2 = (tid + 256) >> 3, lun2 = (tid + 256) & 7;
    uint32_t ld0 = (uint32_t)lrow * SROWB + (uint32_t)lun * 16u;
    uint32_t ld1 = (uint32_t)lrow2 * SROWB + (uint32_t)lun2 * 16u;

    const float2* ryp = g_ry + qg * 16;
    const float2* prp = g_pr2 + qg * 16;
    const float* pw1s = (const float*)(dsm + PW1S);
    const float* pb1s = (const float*)(dsm + PB1S);
    const float* pb2s = (const float*)(dsm + PB2S);
    const float* whs  = (const float*)(dsm + WHS);

    for (int t = 0; t < T_; t++) {
        // ================= Q phase =================
        {
            float a = 0.f;
            if (lane < 8) {
                float zacc = 0.f;
                const float* zp = g_Zpart + qb * 32 + qg * 8 + lane;
                #pragma unroll
                for (int p = 0; p < 8; p++) zacc += __ldcg(zp + p * (B_ * 32));
                a = zacc + g_Xproj[((t * B_ + qb) * 4 + qg) * 8 + lane];
            }
            float sv, cv;
            __sincosf(a * 0.5f, &sv, &cv);

            float re[8], im[8];
            #pragma unroll
            for (int r = 0; r < 8; r++) { re[r] = 0.f; im[r] = 0.f; }
            if (lane == 0) re[0] = 1.f;

            #pragma unroll
            for (int q = 0; q < 5; q++) {
                int d = 16 >> q;
                float c = __shfl_sync(FULL, cv, q);
                float s = __shfl_sync(FULL, sv, q);
                #pragma unroll
                for (int r = 0; r < 8; r++) {
                    float pr = __shfl_xor_sync(FULL, re[r], d);
                    float pi = __shfl_xor_sync(FULL, im[r], d);
                    re[r] = c * re[r] + s * pi;
                    im[r] = c * im[r] - s * pr;
                }
            }
            #pragma unroll
            for (int q = 5; q < 8; q++) {
                int str = 1 << (7 - q);
                float c = __shfl_sync(FULL, cv, q);
                float s = __shfl_sync(FULL, sv, q);
                #pragma unroll
                for (int a0 = 0; a0 < 8; a0++) {
                    if (a0 & str) continue;
                    int b0 = a0 | str;
                    float tr0 = re[a0], ti0 = im[a0], tr1 = re[b0], ti1 = im[b0];
                    re[a0] = c * tr0 + s * ti1;
                    im[a0] = c * ti0 - s * tr1;
                    re[b0] = c * tr1 + s * ti0;
                    im[b0] = c * ti1 - s * tr0;
                }
            }

            #pragma unroll
            for (int l = 0; l < 2; l++) {
                #pragma unroll
                for (int q = 0; q < 5; q++) {
                    float2 ys = ryp[l * 8 + q];
                    int d = 16 >> q;
                    int hi = (lane >> (4 - q)) & 1;
                    float sgn = hi ? ys.y : -ys.y;
                    #pragma unroll
                    for (int r = 0; r < 8; r++) {
                        float pr = __shfl_xor_sync(FULL, re[r], d);
                        float pi = __shfl_xor_sync(FULL, im[r], d);
                        re[r] = ys.x * re[r] + sgn * pr;
                        im[r] = ys.x * im[r] + sgn * pi;
                    }
                }
                #pragma unroll
                for (int q = 5; q < 8; q++) {
                    float2 ys = ryp[l * 8 + q];
                    int str = 1 << (7 - q);
                    #pragma unroll
                    for (int a0 = 0; a0 < 8; a0++) {
                        if (a0 & str) continue;
                        int b0 = a0 | str;
                        float tr0 = re[a0], ti0 = im[a0], tr1 = re[b0], ti1 = im[b0];
                        re[a0] = ys.x * tr0 - ys.y * tr1;
                        im[a0] = ys.x * ti0 - ys.y * ti1;
                        re[b0] = ys.y * tr0 + ys.x * tr1;
                        im[b0] = ys.y * ti0 + ys.x * ti1;
                    }
                }
                if (l == 0) {
                    float2 pl = g_pl2[(qg * 2 + l) * 32 + lane];
                    #pragma unroll
                    for (int r = 0; r < 8; r++) {
                        float nr = pl.x * re[r] - pl.y * im[r];
                        im[r] = pl.x * im[r] + pl.y * re[r];
                        re[r] = nr;
                    }
                    #pragma unroll
                    for (int r = 0; r < 8; r++) {
                        float2 pq = prp[l * 8 + r];
                        float nr = pq.x * re[r] - pq.y * im[r];
                        im[r] = pq.x * im[r] + pq.y * re[r];
                        re[r] = nr;
                    }
                }
                #pragma unroll
                for (int ct = 0; ct < 4; ct++) {
                    int d = 8 >> ct, cb = 4 - ct;
                    int cbit = (lane >> cb) & 1;
                    #pragma unroll
                    for (int r = 0; r < 8; r++) {
                        float pr = __shfl_xor_sync(FULL, re[r], d);
                        float pi = __shfl_xor_sync(FULL, im[r], d);
                        re[r] = cbit ? pr : re[r];
                        im[r] = cbit ? pi : im[r];
                    }
                }
                {
                    int cbit = lane & 1;
                    #pragma unroll
                    for (int r = 0; r < 4; r++) {
                        float t1 = re[r], t2 = re[r + 4];
                        re[r]     = cbit ? t2 : t1;
                        re[r + 4] = cbit ? t1 : t2;
                        t1 = im[r]; t2 = im[r + 4];
                        im[r]     = cbit ? t2 : t1;
                        im[r + 4] = cbit ? t1 : t2;
                    }
                }
                {
                    float tt;
                    tt = re[4]; re[4] = re[6]; re[6] = tt;
                    tt = re[5]; re[5] = re[7]; re[7] = tt;
                    tt = im[4]; im[4] = im[6]; im[6] = tt;
                    tt = im[5]; im[5] = im[7]; im[7] = tt;
                }
                {
                    float tt;
                    tt = re[2]; re[2] = re[3]; re[3] = tt;
                    tt = re[6]; re[6] = re[7]; re[7] = tt;
                    tt = im[2]; im[2] = im[3]; im[3] = tt;
                    tt = im[6]; im[6] = im[7]; im[7] = tt;
                }
            }

            float p0 = re[0]*re[0]+im[0]*im[0], p1 = re[1]*re[1]+im[1]*im[1];
            float p2 = re[2]*re[2]+im[2]*im[2], p3 = re[3]*re[3]+im[3]*im[3];
            float p4 = re[4]*re[4]+im[4]*im[4], p5 = re[5]*re[5]+im[5]*im[5];
            float p6 = re[6]*re[6]+im[6]*im[6], p7 = re[7]*re[7]+im[7]*im[7];
            float S = p0+p1+p2+p3+p4+p5+p6+p7;
            float z[8];
            #pragma unroll
            for (int q = 0; q < 5; q++)
                z[q] = ((lane >> (4 - q)) & 1) ? -S : S;
            z[5] = (p0+p1+p2+p3) - (p4+p5+p6+p7);
            z[6] = (p0+p1+p4+p5) - (p2+p3+p6+p7);
            z[7] = (p0+p2+p4+p6) - (p1+p3+p5+p7);
            #pragma unroll
            for (int q = 0; q < 8; q++) {
                #pragma unroll
                for (int o = 16; o; o >>= 1) z[q] += __shfl_xor_sync(FULL, z[q], o);
            }

            int row = qb * 4 + qg;
            #pragma unroll
            for (int j = 0; j < 16; j++) {
                int col = j * 32 + lane;
                float a2 = pb1s[col];
                #pragma unroll
                for (int q = 0; q < 8; q++) a2 += z[q] * pw1s[q * H_ + col];
                a2 = fmaxf(a2, 0.f);
                g_H1f[row * H_ + col] = __float2half(a2);
            }
        }
        groupbar(grp);

        // ================= G phase: GEMM + LSTM + h-projection =================
        {
            float* outt = out + (size_t)t * (B_ * H_);
            // issue all 8 A-chunk loads as separate groups
            #pragma unroll
            for (int c = 0; c < 8; c++) {
                uint32_t sb = s0 + PA + c * PABUF;
                int kb = c * 64;
                cp16cg(sb + ld0, Af + (size_t)lrow * H_ + kb + lun * 8);
                cp16cg(sb + ld1, Af + (size_t)lrow2 * H_ + kb + lun2 * 8);
                CP_COMMIT();
            }
            float acc[4][4];
            #pragma unroll
            for (int j = 0; j < 4; j++)
                #pragma unroll
                for (int r = 0; r < 4; r++) acc[j][r] = 0.f;

            #define GSTEP(CC, NW) { \
                cp_wait<NW>(); \
                __syncthreads(); \
                uint32_t abuf = s0 + PA + (CC) * PABUF; \
                uint32_t bko = (uint32_t)(CC) * 128u; \
                _Pragma("unroll") \
                for (int kk = 0; kk < 4; kk++) { \
                    uint32_t kb2 = kk * 32; \
                    uint32_t af[4], bf2[2][4]; \
                    ldm4(abuf + aOff + kb2, af); \
                    ldm4(s0 + PB + bOff + bko + kb2, bf2[0]); \
                    ldm4(s0 + PB + bOff + 16 * BROWB + bko + kb2, bf2[1]); \
                    _Pragma("unroll") \
                    for (int j = 0; j < 4; j++) { \
                        int p = j >> 1, sb2 = j & 1; \
                        mma_f16(acc[j], af, bf2[p][sb2], bf2[p][2 + sb2]); \
                    } \
                } }
            GSTEP(0, 7) GSTEP(1, 6) GSTEP(2, 5) GSTEP(3, 4)
            GSTEP(4, 3) GSTEP(5, 2) GSTEP(6, 1) GSTEP(7, 0)
            #undef GSTEP
            __syncthreads();   // all A buffers consumed before aliasing as sp

            // stage preact (aliases A chunk buffers 0/1)
            float* sp = (float*)(dsm + PA);
            int r0 = wm + (lane >> 2);
            #pragma unroll
            for (int j = 0; j < 4; j++) {
                int cc = wn + j * 8 + (lane & 3) * 2;
                sp[r0 * EPAD + cc]           = acc[j][0];
                sp[r0 * EPAD + cc + 1]       = acc[j][1];
                sp[(r0 + 8) * EPAD + cc]     = acc[j][2];
                sp[(r0 + 8) * EPAD + cc + 1] = acc[j][3];
            }
            __syncthreads();

            float* hs = (float*)(dsm + HSOFF);
            bool last = (t == T_ - 1);
            #pragma unroll
            for (int jj = 0; jj < 4; jj++) {
                int e = tid + 256 * jj;
                int bi = e >> 6, col = e & 63;
                float bias = pb2s[col];
                float fv = sigmoidf_(sp[(bi * 4 + 0) * EPAD + col] + bias);
                float iv = sigmoidf_(sp[(bi * 4 + 1) * EPAD + col] + bias);
                float uv = tanhf   (sp[(bi * 4 + 2) * EPAD + col] + bias);
                float ov = sigmoidf_(sp[(bi * 4 + 3) * EPAD + col] + bias);
                float cc2 = fv * cs[e] + iv * uv;
                float hh2 = ov * tanhf(cc2);
                cs[e] = cc2;
                int batch = mt * 16 + bi;
                int idx = batch * H_ + n0 + col;
                outt[idx] = hh2;
                hs[bi * 64 + col] = hh2;
                if (last) {
                    out[(size_t)T_ * B_ * H_ + idx] = hh2;
                    out[(size_t)T_ * B_ * H_ + B_ * H_ + idx] = cc2;
                }
            }
            __syncthreads();

            #pragma unroll
            for (int jj = 0; jj < 2; jj++) {
                int idx2 = tid + 256 * jj;
                int bi = idx2 >> 5, o = idx2 & 31;
                const float* hh = hs + bi * 64;
                const float* wr = whs + o;
                float sacc = 0.f;
                #pragma unroll 16
                for (int c2 = 0; c2 < 64; c2++) sacc += hh[c2] * wr[c2 * 32];
                __stcg(g_Zpart + nt * (B_ * 32) + (mt * 16 + bi) * 32 + o, sacc);
            }
        }
        if (t < T_ - 1) groupbar(grp);
    }
}

// ---------------- host ----------------
extern "C" void kernel_launch(void* const* d_in, const int* in_sizes, int n_in,
                              void* d_out, int out_size) {
    const float* inputs = (const float*)d_in[0];
    const float* qpf = (const float*)d_in[1];
    const float* qpi = (const float*)d_in[2];
    const float* qpu = (const float*)d_in[3];
    const float* qpo = (const float*)d_in[4];
    const float* Wf  = (const float*)d_in[5];
    const float* bf  = (const float*)d_in[6];
    const float* Wi  = (const float*)d_in[7];
    const float* bi  = (const float*)d_in[8];
    const float* Wu  = (const float*)d_in[9];
    const float* bu  = (const float*)d_in[10];
    const float* Wo  = (const float*)d_in[11];
    const float* bo  = (const float*)d_in[12];
    const float* pW1 = (const float*)d_in[13];
    const float* pb1 = (const float*)d_in[14];
    const float* pW2 = (const float*)d_in[15];
    const float* pb2 = (const float*)d_in[16];
    float* out = (float*)d_out;

    cudaFuncSetAttribute(qlstm_kernel, cudaFuncAttributeMaxDynamicSharedMemorySize, SMEM_DYN);
    cudaFuncSetAttribute(xproj_kernel, cudaFuncAttributeMaxDynamicSharedMemorySize, XP3_SMEM);

    bprep_kernel<<<(H_ * H_) / 256, 256>>>(pW2);
    whprep_kernel<<<(H_ * 32) / 256, 256>>>(Wf, Wi, Wu, Wo, bf, bi, bu, bo);
    tabprep_kernel<<<1, 256>>>(qpf, qpi, qpu, qpo);
    xproj_kernel<<<(T_ * B_) / 64, 256, XP3_SMEM>>>(inputs);
    qlstm_kernel<<<128, 256, SMEM_DYN>>>(pW1, pb1, pb2, out);
}

// round 15
// speedup vs baseline: 1.6229x; 1.0035x over previous
#include <cuda_runtime.h>
#include <cuda_bf16.h>
#include <cuda_fp16.h>
#include <math.h>
#include <stdint.h>

#define T_  64
#define B_  256
#define D_  512
#define H_  512

// ---------------- device scratch (allocation-free rule) ----------------
__device__ __half g_H1f[B_ * 4 * H_];          // fp16(H1), row = b*4 + gate
__device__ __half g_Bf[H_ * H_];               // fp16(pW2^T), [n][k]
__device__ __nv_bfloat16 g_Wxh[32 * D_];       // hi(Wx^T) [o][k] for xproj
__device__ __nv_bfloat16 g_Wxl[32 * D_];       // lo(Wx^T)
__device__ float g_bx[32];                     // gate bias vector
__device__ float g_Xproj[T_ * B_ * 32];        // x_t @ W + b, [t*B+b][g*8+q]
__device__ float g_Zpart[B_ * 256];            // [batch][p][32] partial h-projections
__device__ float g_Wh2t[H_ * 32];              // W[D+col][g*8+q] as [col][32]
__device__ float2 g_ry[4 * 2 * 8];             // (cy,sy) per (g,l,q)
__device__ float2 g_pl2[4 * 2 * 32];           // lane-deferred RZ phase per (g,l,lane)
__device__ float2 g_pr2[4 * 2 * 8];            // reg-deferred RZ phase per (g,l,r)
__device__ int g_gcnt[16 * 32];                // padded: one 128B line per group
__device__ volatile int g_ggen[16 * 32];

// ---------------- PTX helpers ----------------
__device__ __forceinline__ uint32_t smem_u32(const void* p) {
    uint32_t a;
    asm("{ .reg .u64 t; cvta.to.shared.u64 t, %1; cvt.u32.u64 %0, t; }" : "=r"(a) : "l"(p));
    return a;
}
__device__ __forceinline__ void cp16cg(uint32_t dst, const void* src) {
    asm volatile("cp.async.cg.shared.global [%0], [%1], 16;" :: "r"(dst), "l"(src) : "memory");
}
#define CP_COMMIT() asm volatile("cp.async.commit_group;" ::: "memory")
template<int N> __device__ __forceinline__ void cp_wait() {
    asm volatile("cp.async.wait_group %0;" :: "n"(N) : "memory");
}
__device__ __forceinline__ void ldm4(uint32_t addr, uint32_t* r) {
    asm volatile("ldmatrix.sync.aligned.m8n8.x4.shared.b16 {%0,%1,%2,%3}, [%4];"
        : "=r"(r[0]), "=r"(r[1]), "=r"(r[2]), "=r"(r[3]) : "r"(addr));
}
__device__ __forceinline__ void mma_bf16(float* c, const uint32_t* a, uint32_t b0, uint32_t b1) {
    asm volatile(
        "mma.sync.aligned.m16n8k16.row.col.f32.bf16.bf16.f32 "
        "{%0,%1,%2,%3}, {%4,%5,%6,%7}, {%8,%9}, {%0,%1,%2,%3};"
        : "+f"(c[0]), "+f"(c[1]), "+f"(c[2]), "+f"(c[3])
        : "r"(a[0]), "r"(a[1]), "r"(a[2]), "r"(a[3]), "r"(b0), "r"(b1));
}
__device__ __forceinline__ void mma_f16(float* c, const uint32_t* a, uint32_t b0, uint32_t b1) {
    asm volatile(
        "mma.sync.aligned.m16n8k16.row.col.f32.f16.f16.f32 "
        "{%0,%1,%2,%3}, {%4,%5,%6,%7}, {%8,%9}, {%0,%1,%2,%3};"
        : "+f"(c[0]), "+f"(c[1]), "+f"(c[2]), "+f"(c[3])
        : "r"(a[0]), "r"(a[1]), "r"(a[2]), "r"(a[3]), "r"(b0), "r"(b1));
}
__device__ __forceinline__ float sigmoidf_(float x) { return 1.f / (1.f + expf(-x)); }

// ---------------- group barrier: 8 blocks (one m-tile group), padded lines ---
__device__ __forceinline__ void groupbar(int grp) {
    __syncthreads();
    if (threadIdx.x == 0) {
        __threadfence();
        int gen = g_ggen[grp * 32];
        if (atomicAdd(&g_gcnt[grp * 32], 1) == 7) {
            g_gcnt[grp * 32] = 0;
            __threadfence();
            g_ggen[grp * 32] = gen + 1;
        } else {
            while (g_ggen[grp * 32] == gen) { }
        }
    }
    __syncthreads();
}

// ---------------- prep kernels ----------------
// pW2 (K,N) -> transposed single fp16 [n][k]
__global__ void bprep_kernel(const float* __restrict__ pW2) {
    int i = blockIdx.x * blockDim.x + threadIdx.x;
    int n = i >> 9, k = i & 511;
    g_Bf[i] = __float2half(pW2[k * H_ + n]);
}

__global__ void whprep_kernel(
    const float* __restrict__ Wf, const float* __restrict__ Wi,
    const float* __restrict__ Wu, const float* __restrict__ Wo,
    const float* __restrict__ bf, const float* __restrict__ bi,
    const float* __restrict__ bu, const float* __restrict__ bo)
{
    int i = blockIdx.x * blockDim.x + threadIdx.x;   // 0..16383
    {
        int col = i >> 5, o = i & 31, g = o >> 3, q = o & 7;
        const float* W = (g == 0) ? Wf : (g == 1) ? Wi : (g == 2) ? Wu : Wo;
        g_Wh2t[i] = W[(D_ + col) * 8 + q];
    }
    {
        int o = i >> 9, k = i & 511, g = o >> 3, q = o & 7;
        const float* W = (g == 0) ? Wf : (g == 1) ? Wi : (g == 2) ? Wu : Wo;
        float v = W[k * 8 + q];
        __nv_bfloat16 hi = __float2bfloat16(v);
        __nv_bfloat16 lo = __float2bfloat16(v - __bfloat162float(hi));
        g_Wxh[i] = hi; g_Wxl[i] = lo;
    }
    if (i < 32) {
        int g = i >> 3, q = i & 7;
        const float* bb = (g == 0) ? bf : (g == 1) ? bi : (g == 2) ? bu : bo;
        g_bx[i] = bb[q];
    }
}

__global__ void tabprep_kernel(
    const float* __restrict__ qpf, const float* __restrict__ qpi,
    const float* __restrict__ qpu, const float* __restrict__ qpo)
{
    int i = threadIdx.x;   // 0..255
    const float* qps[4] = {qpf, qpi, qpu, qpo};
    if (i < 64) {
        int g = i >> 4, l = (i >> 3) & 1, q = i & 7;
        const float* qp = qps[g];
        float th = qp[(l * 8 + q) * 3 + 0] * 0.5f;
        g_ry[i] = make_float2(cosf(th), sinf(th));
        int r = q;
        float prr = 1.f, pri = 0.f;
        #pragma unroll
        for (int qq = 5; qq < 8; qq++) {
            float tz = qp[(l * 8 + qq) * 3 + 1] * 0.5f;
            float cz = cosf(tz), sz = sinf(tz);
            float zn = ((r >> (7 - qq)) & 1) ? sz : -sz;
            float nr = prr * cz - pri * zn;
            float ni = prr * zn + pri * cz;
            prr = nr; pri = ni;
        }
        g_pr2[i] = make_float2(prr, pri);
    }
    {
        int g = i >> 6, l = (i >> 5) & 1, ln = i & 31;
        const float* qp = qps[g];
        float prr = 1.f, pri = 0.f;
        #pragma unroll
        for (int q = 0; q < 5; q++) {
            float tz = qp[(l * 8 + q) * 3 + 1] * 0.5f;
            float cz = cosf(tz), sz = sinf(tz);
            float zn = ((ln >> (4 - q)) & 1) ? sz : -sz;
            float nr = prr * cz - pri * zn;
            float ni = prr * zn + pri * cz;
            prr = nr; pri = ni;
        }
        g_pl2[i] = make_float2(prr, pri);
    }
}

// ---------------- xproj v4: HMMA GEMM, 256 threads, 8 warps ----------------
#define XROWB 1040u
#define XA_H 0u
#define XA_L 66560u
#define XB_H 133120u
#define XB_L 166400u
#define XP3_SMEM 199680

__global__ __launch_bounds__(256, 1) void xproj_kernel(const float* __restrict__ inputs)
{
    extern __shared__ __align__(16) char xsm[];
    uint32_t s0 = smem_u32(xsm);
    int tid = threadIdx.x, wid = tid >> 5, lane = tid & 31;
    int m0 = blockIdx.x * 64;

    #pragma unroll
    for (int j = 0; j < 8; j++) {               // B: 2048 16B units
        int u = tid + 256 * j;
        int row = u >> 6, ku = u & 63;
        uint32_t dst = (uint32_t)row * XROWB + (uint32_t)ku * 16u;
        cp16cg(s0 + XB_H + dst, g_Wxh + row * D_ + ku * 8);
        cp16cg(s0 + XB_L + dst, g_Wxl + row * D_ + ku * 8);
    }
    CP_COMMIT();

    #pragma unroll
    for (int j = 0; j < 32; j++) {              // A: 8192 float4 units
        int u = tid + 256 * j;
        int row = u >> 7, f4 = u & 127;
        float4 xv = *(const float4*)(inputs + (size_t)(m0 + row) * D_ + f4 * 4);
        __nv_bfloat16 h0 = __float2bfloat16(xv.x), h1 = __float2bfloat16(xv.y);
        __nv_bfloat16 h2 = __float2bfloat16(xv.z), h3 = __float2bfloat16(xv.w);
        __nv_bfloat16 l0 = __float2bfloat16(xv.x - __bfloat162float(h0));
        __nv_bfloat16 l1 = __float2bfloat16(xv.y - __bfloat162float(h1));
        __nv_bfloat16 l2 = __float2bfloat16(xv.z - __bfloat162float(h2));
        __nv_bfloat16 l3 = __float2bfloat16(xv.w - __bfloat162float(h3));
        uint2 ph, pl;
        ph.x = ((uint32_t)__bfloat16_as_ushort(h1) << 16) | __bfloat16_as_ushort(h0);
        ph.y = ((uint32_t)__bfloat16_as_ushort(h3) << 16) | __bfloat16_as_ushort(h2);
        pl.x = ((uint32_t)__bfloat16_as_ushort(l1) << 16) | __bfloat16_as_ushort(l0);
        pl.y = ((uint32_t)__bfloat16_as_ushort(l3) << 16) | __bfloat16_as_ushort(l2);
        uint32_t off = (uint32_t)row * XROWB + (uint32_t)f4 * 8u;
        *(uint2*)(xsm + XA_H + off) = ph;
        *(uint2*)(xsm + XA_L + off) = pl;
    }
    cp_wait<0>();
    __syncthreads();

    int wm = (wid >> 1) * 16, nh = wid & 1;
    float acc[2][4];
    #pragma unroll
    for (int j = 0; j < 2; j++)
        #pragma unroll
        for (int r = 0; r < 4; r++) acc[j][r] = 0.f;

    uint32_t aOff = (uint32_t)(wm + (lane & 15)) * XROWB + (uint32_t)((lane >> 4) << 4);
    uint32_t bOff = (uint32_t)(nh * 16 + (lane & 15)) * XROWB + (uint32_t)((lane >> 4) << 4);

    #pragma unroll 4
    for (int k16 = 0; k16 < 32; k16++) {
        uint32_t kb = (uint32_t)k16 * 32u;
        uint32_t ah[4], al[4], bh[4], bl[4];
        ldm4(s0 + XA_H + aOff + kb, ah);
        ldm4(s0 + XA_L + aOff + kb, al);
        ldm4(s0 + XB_H + bOff + kb, bh);
        ldm4(s0 + XB_L + bOff + kb, bl);
        #pragma unroll
        for (int j = 0; j < 2; j++) {
            mma_bf16(acc[j], ah, bh[j], bh[2 + j]);
            mma_bf16(acc[j], ah, bl[j], bl[2 + j]);
            mma_bf16(acc[j], al, bh[j], bh[2 + j]);
        }
    }

    int r0 = m0 + wm + (lane >> 2);
    #pragma unroll
    for (int j = 0; j < 2; j++) {
        int col = (nh * 2 + j) * 8 + (lane & 3) * 2;
        float b0 = g_bx[col], b1 = g_bx[col + 1];
        *(float2*)(g_Xproj + (size_t)r0 * 32 + col)       = make_float2(acc[j][0] + b0, acc[j][1] + b1);
        *(float2*)(g_Xproj + (size_t)(r0 + 8) * 32 + col) = make_float2(acc[j][2] + b0, acc[j][3] + b1);
    }
}

// ---------------- the persistent recurrence kernel ----------------
// smem: B resident fp16; A 4 chunks of K=128 (row stride 272B); resident tables.
#define BROWB 1040u
#define PB    0u
#define PA    66560u
#define PABUF 17408u
#define AROWB 272u
#define PW1S  140288u
#define WHS   156672u
#define PB1S  164864u
#define PB2S  166912u
#define CS    167168u
#define HSOFF 171264u
#define SMEM_DYN 175360
#define EPAD 68

__global__ __launch_bounds__(256, 1) void qlstm_kernel(
    const float* __restrict__ pW1, const float* __restrict__ pb1,
    const float* __restrict__ pb2, float* __restrict__ out)
{
    extern __shared__ __align__(16) char dsm[];
    const unsigned FULL = 0xffffffffu;
    uint32_t s0 = smem_u32(dsm);
    int tid = threadIdx.x, wid = tid >> 5, lane = tid & 31;
    int bid = blockIdx.x;
    int nt = bid & 7, mt = bid >> 3;
    int grp = mt;
    int n0 = nt * 64, m0 = mt * 64;

    int sidx = bid * 8 + wid;
    int qb = sidx >> 2, qg = sidx & 3;

    // ---- stage resident smem (one-time) ----
    #pragma unroll
    for (int j = 0; j < 16; j++) {              // B tile (single fp16)
        int u = tid + 256 * j;
        int row = u >> 6, ku = u & 63;
        cp16cg(s0 + PB + (uint32_t)row * BROWB + (uint32_t)ku * 16u,
               g_Bf + (size_t)(n0 + row) * H_ + ku * 8);
    }
    #pragma unroll
    for (int j = 0; j < 4; j++) {               // pW1 (16KB)
        int u = tid + 256 * j;
        cp16cg(s0 + PW1S + (uint32_t)u * 16u, pW1 + u * 4);
    }
    #pragma unroll
    for (int j = 0; j < 2; j++) {               // Wh tile (8KB)
        int u = tid + 256 * j;
        cp16cg(s0 + WHS + (uint32_t)u * 16u, g_Wh2t + (size_t)n0 * 32 + u * 4);
    }
    if (tid < 128) cp16cg(s0 + PB1S + (uint32_t)tid * 16u, pb1 + tid * 4);
    if (tid < 16)  cp16cg(s0 + PB2S + (uint32_t)tid * 16u, pb2 + n0 + tid * 4);
    CP_COMMIT();

    float* cs = (float*)(dsm + CS);
    #pragma unroll
    for (int j = 0; j < 4; j++) cs[tid + 256 * j] = 0.f;
    // zero this block's Zpart slice: batches bid*2, bid*2+1 -> 512 floats
    __stcg(g_Zpart + bid * 512 + tid, 0.f);
    __stcg(g_Zpart + bid * 512 + 256 + tid, 0.f);
    cp_wait<0>();
    groupbar(grp);

    // ---- hoisted constants ----
    const __half* Af = g_H1f + (size_t)m0 * H_;
    int wm = (wid >> 1) * 16, wn = (wid & 1) * 32;
    uint32_t aOff = (uint32_t)(wm + (lane & 15)) * AROWB + (uint32_t)((lane >> 4) << 4);
    uint32_t bOff = (uint32_t)(wn + (lane & 15)) * BROWB + (uint32_t)((lane >> 4) << 4);
    // A chunk load coords: chunk = 64 rows x 128 fp16, 1024 16B units, 4/thread
    int arow[4], aun[4];
    uint32_t adst[4];
    #pragma unroll
    for (int j = 0; j < 4; j++) {
        int u = tid + 256 * j;
        arow[j] = u >> 4; aun[j] = u & 15;
        adst[j] = (uint32_t)arow[j] * AROWB + (uint32_t)aun[j] * 16u;
    }

    const float2* ryp = g_ry + qg * 16;
    const float2* prp = g_pr2 + qg * 16;
    const float* pw1s = (const float*)(dsm + PW1S);
    const float* pb1s = (const float*)(dsm + PB1S);
    const float* pb2s = (const float*)(dsm + PB2S);
    const float* whs  = (const float*)(dsm + WHS);

    for (int t = 0; t < T_; t++) {
        // ================= Q phase =================
        {
            float a = 0.f;
            if (lane < 8) {
                float xp = g_Xproj[((t * B_ + qb) * 4 + qg) * 8 + lane];
                float zacc = 0.f;
                const float* zp = g_Zpart + qb * 256 + qg * 8 + lane;
                #pragma unroll
                for (int p = 0; p < 8; p++) zacc += __ldcg(zp + p * 32);
                a = zacc + xp;
            }
            float sv, cv;
            __sincosf(a * 0.5f, &sv, &cv);

            float re[8], im[8];
            #pragma unroll
            for (int r = 0; r < 8; r++) { re[r] = 0.f; im[r] = 0.f; }
            if (lane == 0) re[0] = 1.f;

            #pragma unroll
            for (int q = 0; q < 5; q++) {
                int d = 16 >> q;
                float c = __shfl_sync(FULL, cv, q);
                float s = __shfl_sync(FULL, sv, q);
                #pragma unroll
                for (int r = 0; r < 8; r++) {
                    float pr = __shfl_xor_sync(FULL, re[r], d);
                    float pi = __shfl_xor_sync(FULL, im[r], d);
                    re[r] = c * re[r] + s * pi;
                    im[r] = c * im[r] - s * pr;
                }
            }
            #pragma unroll
            for (int q = 5; q < 8; q++) {
                int str = 1 << (7 - q);
                float c = __shfl_sync(FULL, cv, q);
                float s = __shfl_sync(FULL, sv, q);
                #pragma unroll
                for (int a0 = 0; a0 < 8; a0++) {
                    if (a0 & str) continue;
                    int b0 = a0 | str;
                    float tr0 = re[a0], ti0 = im[a0], tr1 = re[b0], ti1 = im[b0];
                    re[a0] = c * tr0 + s * ti1;
                    im[a0] = c * ti0 - s * tr1;
                    re[b0] = c * tr1 + s * ti0;
                    im[b0] = c * ti1 - s * tr0;
                }
            }

            #pragma unroll
            for (int l = 0; l < 2; l++) {
                #pragma unroll
                for (int q = 0; q < 5; q++) {
                    float2 ys = ryp[l * 8 + q];
                    int d = 16 >> q;
                    int hi = (lane >> (4 - q)) & 1;
                    float sgn = hi ? ys.y : -ys.y;
                    #pragma unroll
                    for (int r = 0; r < 8; r++) {
                        float pr = __shfl_xor_sync(FULL, re[r], d);
                        float pi = __shfl_xor_sync(FULL, im[r], d);
                        re[r] = ys.x * re[r] + sgn * pr;
                        im[r] = ys.x * im[r] + sgn * pi;
                    }
                }
                #pragma unroll
                for (int q = 5; q < 8; q++) {
                    float2 ys = ryp[l * 8 + q];
                    int str = 1 << (7 - q);
                    #pragma unroll
                    for (int a0 = 0; a0 < 8; a0++) {
                        if (a0 & str) continue;
                        int b0 = a0 | str;
                        float tr0 = re[a0], ti0 = im[a0], tr1 = re[b0], ti1 = im[b0];
                        re[a0] = ys.x * tr0 - ys.y * tr1;
                        im[a0] = ys.x * ti0 - ys.y * ti1;
                        re[b0] = ys.y * tr0 + ys.x * tr1;
                        im[b0] = ys.y * ti0 + ys.x * ti1;
                    }
                }
                if (l == 0) {
                    float2 pl = g_pl2[(qg * 2 + l) * 32 + lane];
                    #pragma unroll
                    for (int r = 0; r < 8; r++) {
                        float nr = pl.x * re[r] - pl.y * im[r];
                        im[r] = pl.x * im[r] + pl.y * re[r];
                        re[r] = nr;
                    }
                    #pragma unroll
                    for (int r = 0; r < 8; r++) {
                        float2 pq = prp[l * 8 + r];
                        float nr = pq.x * re[r] - pq.y * im[r];
                        im[r] = pq.x * im[r] + pq.y * re[r];
                        re[r] = nr;
                    }
                }
                #pragma unroll
                for (int ct = 0; ct < 4; ct++) {
                    int d = 8 >> ct, cb = 4 - ct;
                    int cbit = (lane >> cb) & 1;
                    #pragma unroll
                    for (int r = 0; r < 8; r++) {
                        float pr = __shfl_xor_sync(FULL, re[r], d);
                        float pi = __shfl_xor_sync(FULL, im[r], d);
                        re[r] = cbit ? pr : re[r];
                        im[r] = cbit ? pi : im[r];
                    }
                }
                {
                    int cbit = lane & 1;
                    #pragma unroll
                    for (int r = 0; r < 4; r++) {
                        float t1 = re[r], t2 = re[r + 4];
                        re[r]     = cbit ? t2 : t1;
                        re[r + 4] = cbit ? t1 : t2;
                        t1 = im[r]; t2 = im[r + 4];
                        im[r]     = cbit ? t2 : t1;
                        im[r + 4] = cbit ? t1 : t2;
                    }
                }
                {
                    float tt;
                    tt = re[4]; re[4] = re[6]; re[6] = tt;
                    tt = re[5]; re[5] = re[7]; re[7] = tt;
                    tt = im[4]; im[4] = im[6]; im[6] = tt;
                    tt = im[5]; im[5] = im[7]; im[7] = tt;
                }
                {
                    float tt;
                    tt = re[2]; re[2] = re[3]; re[3] = tt;
                    tt = re[6]; re[6] = re[7]; re[7] = tt;
                    tt = im[2]; im[2] = im[3]; im[3] = tt;
                    tt = im[6]; im[6] = im[7]; im[7] = tt;
                }
            }

            float p0 = re[0]*re[0]+im[0]*im[0], p1 = re[1]*re[1]+im[1]*im[1];
            float p2 = re[2]*re[2]+im[2]*im[2], p3 = re[3]*re[3]+im[3]*im[3];
            float p4 = re[4]*re[4]+im[4]*im[4], p5 = re[5]*re[5]+im[5]*im[5];
            float p6 = re[6]*re[6]+im[6]*im[6], p7 = re[7]*re[7]+im[7]*im[7];
            float S = p0+p1+p2+p3+p4+p5+p6+p7;
            float z[8];
            #pragma unroll
            for (int q = 0; q < 5; q++)
                z[q] = ((lane >> (4 - q)) & 1) ? -S : S;
            z[5] = (p0+p1+p2+p3) - (p4+p5+p6+p7);
            z[6] = (p0+p1+p4+p5) - (p2+p3+p6+p7);
            z[7] = (p0+p2+p4+p6) - (p1+p3+p5+p7);
            #pragma unroll
            for (int q = 0; q < 8; q++) {
                #pragma unroll
                for (int o = 16; o; o >>= 1) z[q] += __shfl_xor_sync(FULL, z[q], o);
            }

            int row = qb * 4 + qg;
            #pragma unroll
            for (int j = 0; j < 16; j++) {
                int col = j * 32 + lane;
                float a2 = pb1s[col];
                #pragma unroll
                for (int q = 0; q < 8; q++) a2 += z[q] * pw1s[q * H_ + col];
                a2 = fmaxf(a2, 0.f);
                g_H1f[row * H_ + col] = __float2half(a2);
            }
        }
        groupbar(grp);

        // ================= G phase: GEMM + LSTM + h-projection =================
        {
            float* outt = out + (size_t)t * (B_ * H_);
            // issue all 4 A-chunk loads (K=128 each) as separate groups
            #pragma unroll
            for (int c = 0; c < 4; c++) {
                uint32_t sb = s0 + PA + c * PABUF;
                int kb = c * 128;
                #pragma unroll
                for (int j = 0; j < 4; j++)
                    cp16cg(sb + adst[j], Af + (size_t)arow[j] * H_ + kb + aun[j] * 8);
                CP_COMMIT();
            }
            float acc[4][4];
            #pragma unroll
            for (int j = 0; j < 4; j++)
                #pragma unroll
                for (int r = 0; r < 4; r++) acc[j][r] = 0.f;

            #define GSTEP(CC, NW) { \
                cp_wait<NW>(); \
                __syncthreads(); \
                uint32_t abuf = s0 + PA + (CC) * PABUF; \
                uint32_t bko = (uint32_t)(CC) * 256u; \
                _Pragma("unroll") \
                for (int kk = 0; kk < 8; kk++) { \
                    uint32_t kb2 = kk * 32; \
                    uint32_t af[4], bf2[2][4]; \
                    ldm4(abuf + aOff + kb2, af); \
                    ldm4(s0 + PB + bOff + bko + kb2, bf2[0]); \
                    ldm4(s0 + PB + bOff + 16 * BROWB + bko + kb2, bf2[1]); \
                    _Pragma("unroll") \
                    for (int j = 0; j < 4; j++) { \
                        int p = j >> 1, sb2 = j & 1; \
                        mma_f16(acc[j], af, bf2[p][sb2], bf2[p][2 + sb2]); \
                    } \
                } }
            GSTEP(0, 3) GSTEP(1, 2) GSTEP(2, 1) GSTEP(3, 0)
            #undef GSTEP
            __syncthreads();   // all A buffers consumed before aliasing as sp

            // stage preact (aliases A chunk buffer 0)
            float* sp = (float*)(dsm + PA);
            int r0 = wm + (lane >> 2);
            #pragma unroll
            for (int j = 0; j < 4; j++) {
                int cc = wn + j * 8 + (lane & 3) * 2;
                sp[r0 * EPAD + cc]           = acc[j][0];
                sp[r0 * EPAD + cc + 1]       = acc[j][1];
                sp[(r0 + 8) * EPAD + cc]     = acc[j][2];
                sp[(r0 + 8) * EPAD + cc + 1] = acc[j][3];
            }
            __syncthreads();

            float* hs = (float*)(dsm + HSOFF);
            bool last = (t == T_ - 1);
            #pragma unroll
            for (int jj = 0; jj < 4; jj++) {
                int e = tid + 256 * jj;
                int bi = e >> 6, col = e & 63;
                float bias = pb2s[col];
                float fv = sigmoidf_(sp[(bi * 4 + 0) * EPAD + col] + bias);
                float iv = sigmoidf_(sp[(bi * 4 + 1) * EPAD + col] + bias);
                float uv = tanhf   (sp[(bi * 4 + 2) * EPAD + col] + bias);
                float ov = sigmoidf_(sp[(bi * 4 + 3) * EPAD + col] + bias);
                float cc2 = fv * cs[e] + iv * uv;
                float hh2 = ov * tanhf(cc2);
                cs[e] = cc2;
                int batch = mt * 16 + bi;
                int idx = batch * H_ + n0 + col;
                outt[idx] = hh2;
                hs[bi * 64 + col] = hh2;
                if (last) {
                    out[(size_t)T_ * B_ * H_ + idx] = hh2;
                    out[(size_t)T_ * B_ * H_ + B_ * H_ + idx] = cc2;
                }
            }
            __syncthreads();

            #pragma unroll
            for (int jj = 0; jj < 2; jj++) {
                int idx2 = tid + 256 * jj;
                int bi = idx2 >> 5, o = idx2 & 31;
                const float* hh = hs + bi * 64;
                const float* wr = whs + o;
                float sacc = 0.f;
                #pragma unroll 16
                for (int c2 = 0; c2 < 64; c2++) sacc += hh[c2] * wr[c2 * 32];
                __stcg(g_Zpart + (mt * 16 + bi) * 256 + nt * 32 + o, sacc);
            }
        }
        if (t < T_ - 1) groupbar(grp);
    }
}

// ---------------- host ----------------
extern "C" void kernel_launch(void* const* d_in, const int* in_sizes, int n_in,
                              void* d_out, int out_size) {
    const float* inputs = (const float*)d_in[0];
    const float* qpf = (const float*)d_in[1];
    const float* qpi = (const float*)d_in[2];
    const float* qpu = (const float*)d_in[3];
    const float* qpo = (const float*)d_in[4];
    const float* Wf  = (const float*)d_in[5];
    const float* bf  = (const float*)d_in[6];
    const float* Wi  = (const float*)d_in[7];
    const float* bi  = (const float*)d_in[8];
    const float* Wu  = (const float*)d_in[9];
    const float* bu  = (const float*)d_in[10];
    const float* Wo  = (const float*)d_in[11];
    const float* bo  = (const float*)d_in[12];
    const float* pW1 = (const float*)d_in[13];
    const float* pb1 = (const float*)d_in[14];
    const float* pW2 = (const float*)d_in[15];
    const float* pb2 = (const float*)d_in[16];
    float* out = (float*)d_out;

    cudaFuncSetAttribute(qlstm_kernel, cudaFuncAttributeMaxDynamicSharedMemorySize, SMEM_DYN);
    cudaFuncSetAttribute(xproj_kernel, cudaFuncAttributeMaxDynamicSharedMemorySize, XP3_SMEM);

    bprep_kernel<<<(H_ * H_) / 256, 256>>>(pW2);
    whprep_kernel<<<(H_ * 32) / 256, 256>>>(Wf, Wi, Wu, Wo, bf, bi, bu, bo);
    tabprep_kernel<<<1, 256>>>(qpf, qpi, qpu, qpo);
    xproj_kernel<<<(T_ * B_) / 64, 256, XP3_SMEM>>>(inputs);
    qlstm_kernel<<<128, 256, SMEM_DYN>>>(pW1, pb1, pb2, out);
}

// round 16
// speedup vs baseline: 1.7228x; 1.0615x over previous
#include <cuda_runtime.h>
#include <cuda_bf16.h>
#include <cuda_fp16.h>
#include <math.h>
#include <stdint.h>

#define T_  64
#define B_  256
#define D_  512
#define H_  512

// ---------------- device scratch (allocation-free rule) ----------------
__device__ __half g_H1f[B_ * 4 * H_];          // fp16(H1), row = b*4 + gate
__device__ __half g_Bf[H_ * H_];               // fp16(pW2^T), [n][k]
__device__ __nv_bfloat16 g_Wxh[32 * D_];       // hi(Wx^T) [o][k] for xproj
__device__ __nv_bfloat16 g_Wxl[32 * D_];       // lo(Wx^T)
__device__ float g_bx[32];                     // gate bias vector
__device__ float g_Xproj[T_ * B_ * 32];        // x_t @ W + b, [t*B+b][g*8+q]
__device__ float g_Zpart[B_ * 256];            // [batch][p][32] partial h-projections
__device__ float g_Wh2t[H_ * 32];              // W[D+col][g*8+q] as [col][32]
__device__ float2 g_ry[4 * 2 * 8];             // (cy,sy) per (g,l,q)
__device__ float2 g_pl2[4 * 2 * 32];           // lane-deferred RZ phase per (g,l,lane)
__device__ float2 g_pr2[4 * 2 * 8];            // reg-deferred RZ phase per (g,l,r)
__device__ int g_gcnt[16 * 32];                // padded: one 128B line per group
__device__ volatile int g_ggen[16 * 32];

// ---------------- PTX helpers ----------------
__device__ __forceinline__ uint32_t smem_u32(const void* p) {
    uint32_t a;
    asm("{ .reg .u64 t; cvta.to.shared.u64 t, %1; cvt.u32.u64 %0, t; }" : "=r"(a) : "l"(p));
    return a;
}
__device__ __forceinline__ void cp16cg(uint32_t dst, const void* src) {
    asm volatile("cp.async.cg.shared.global [%0], [%1], 16;" :: "r"(dst), "l"(src) : "memory");
}
#define CP_COMMIT() asm volatile("cp.async.commit_group;" ::: "memory")
template<int N> __device__ __forceinline__ void cp_wait() {
    asm volatile("cp.async.wait_group %0;" :: "n"(N) : "memory");
}
__device__ __forceinline__ void ldm4(uint32_t addr, uint32_t* r) {
    asm volatile("ldmatrix.sync.aligned.m8n8.x4.shared.b16 {%0,%1,%2,%3}, [%4];"
        : "=r"(r[0]), "=r"(r[1]), "=r"(r[2]), "=r"(r[3]) : "r"(addr));
}
__device__ __forceinline__ void mma_bf16(float* c, const uint32_t* a, uint32_t b0, uint32_t b1) {
    asm volatile(
        "mma.sync.aligned.m16n8k16.row.col.f32.bf16.bf16.f32 "
        "{%0,%1,%2,%3}, {%4,%5,%6,%7}, {%8,%9}, {%0,%1,%2,%3};"
        : "+f"(c[0]), "+f"(c[1]), "+f"(c[2]), "+f"(c[3])
        : "r"(a[0]), "r"(a[1]), "r"(a[2]), "r"(a[3]), "r"(b0), "r"(b1));
}
__device__ __forceinline__ void mma_f16(float* c, const uint32_t* a, uint32_t b0, uint32_t b1) {
    asm volatile(
        "mma.sync.aligned.m16n8k16.row.col.f32.f16.f16.f32 "
        "{%0,%1,%2,%3}, {%4,%5,%6,%7}, {%8,%9}, {%0,%1,%2,%3};"
        : "+f"(c[0]), "+f"(c[1]), "+f"(c[2]), "+f"(c[3])
        : "r"(a[0]), "r"(a[1]), "r"(a[2]), "r"(a[3]), "r"(b0), "r"(b1));
}
// fast activations: __expf + fast divide (~1e-6 rel err, well under budget)
__device__ __forceinline__ float fsigmoid(float x) {
    return __fdividef(1.f, 1.f + __expf(-x));
}
__device__ __forceinline__ float ftanh(float x) {
    x = fminf(fmaxf(x, -15.f), 15.f);          // overflow-safe
    float e = __expf(2.f * x);
    return 1.f - __fdividef(2.f, e + 1.f);
}

// ---------------- group barrier: 8 blocks (one m-tile group), padded lines ---
__device__ __forceinline__ void groupbar(int grp) {
    __syncthreads();
    if (threadIdx.x == 0) {
        __threadfence();
        int gen = g_ggen[grp * 32];
        if (atomicAdd(&g_gcnt[grp * 32], 1) == 7) {
            g_gcnt[grp * 32] = 0;
            __threadfence();
            g_ggen[grp * 32] = gen + 1;
        } else {
            while (g_ggen[grp * 32] == gen) { }
        }
    }
    __syncthreads();
}

// ---------------- merged prep kernel ----------------
// blocks [0,1024): bprep; [1024,1088): whprep; 1088: trig tables.
__global__ void prep_kernel(
    const float* __restrict__ pW2,
    const float* __restrict__ Wf, const float* __restrict__ Wi,
    const float* __restrict__ Wu, const float* __restrict__ Wo,
    const float* __restrict__ bf, const float* __restrict__ bi,
    const float* __restrict__ bu, const float* __restrict__ bo,
    const float* __restrict__ qpf, const float* __restrict__ qpi,
    const float* __restrict__ qpu, const float* __restrict__ qpo)
{
    int blk = blockIdx.x, tid = threadIdx.x;
    if (blk < 1024) {
        int i = blk * 256 + tid;
        int n = i >> 9, k = i & 511;
        g_Bf[i] = __float2half(pW2[k * H_ + n]);
        return;
    }
    if (blk < 1088) {
        int i = (blk - 1024) * 256 + tid;    // 0..16383
        {
            int col = i >> 5, o = i & 31, g = o >> 3, q = o & 7;
            const float* W = (g == 0) ? Wf : (g == 1) ? Wi : (g == 2) ? Wu : Wo;
            g_Wh2t[i] = W[(D_ + col) * 8 + q];
        }
        {
            int o = i >> 9, k = i & 511, g = o >> 3, q = o & 7;
            const float* W = (g == 0) ? Wf : (g == 1) ? Wi : (g == 2) ? Wu : Wo;
            float v = W[k * 8 + q];
            __nv_bfloat16 hi = __float2bfloat16(v);
            __nv_bfloat16 lo = __float2bfloat16(v - __bfloat162float(hi));
            g_Wxh[i] = hi; g_Wxl[i] = lo;
        }
        if (i < 32) {
            int g = i >> 3, q = i & 7;
            const float* bb = (g == 0) ? bf : (g == 1) ? bi : (g == 2) ? bu : bo;
            g_bx[i] = bb[q];
        }
        return;
    }
    // trig tables (one block, 256 threads)
    int i = tid;
    const float* qps[4] = {qpf, qpi, qpu, qpo};
    if (i < 64) {
        int g = i >> 4, l = (i >> 3) & 1, q = i & 7;
        const float* qp = qps[g];
        float th = qp[(l * 8 + q) * 3 + 0] * 0.5f;
        g_ry[i] = make_float2(cosf(th), sinf(th));
        int r = q;
        float prr = 1.f, pri = 0.f;
        #pragma unroll
        for (int qq = 5; qq < 8; qq++) {
            float tz = qp[(l * 8 + qq) * 3 + 1] * 0.5f;
            float cz = cosf(tz), sz = sinf(tz);
            float zn = ((r >> (7 - qq)) & 1) ? sz : -sz;
            float nr = prr * cz - pri * zn;
            float ni = prr * zn + pri * cz;
            prr = nr; pri = ni;
        }
        g_pr2[i] = make_float2(prr, pri);
    }
    {
        int g = i >> 6, l = (i >> 5) & 1, ln = i & 31;
        const float* qp = qps[g];
        float prr = 1.f, pri = 0.f;
        #pragma unroll
        for (int q = 0; q < 5; q++) {
            float tz = qp[(l * 8 + q) * 3 + 1] * 0.5f;
            float cz = cosf(tz), sz = sinf(tz);
            float zn = ((ln >> (4 - q)) & 1) ? sz : -sz;
            float nr = prr * cz - pri * zn;
            float ni = prr * zn + pri * cz;
            prr = nr; pri = ni;
        }
        g_pl2[i] = make_float2(prr, pri);
    }
}

// ---------------- xproj v4: HMMA GEMM, 256 threads, 8 warps ----------------
#define XROWB 1040u
#define XA_H 0u
#define XA_L 66560u
#define XB_H 133120u
#define XB_L 166400u
#define XP3_SMEM 199680

__global__ __launch_bounds__(256, 1) void xproj_kernel(const float* __restrict__ inputs)
{
    extern __shared__ __align__(16) char xsm[];
    uint32_t s0 = smem_u32(xsm);
    int tid = threadIdx.x, wid = tid >> 5, lane = tid & 31;
    int m0 = blockIdx.x * 64;

    #pragma unroll
    for (int j = 0; j < 8; j++) {               // B: 2048 16B units
        int u = tid + 256 * j;
        int row = u >> 6, ku = u & 63;
        uint32_t dst = (uint32_t)row * XROWB + (uint32_t)ku * 16u;
        cp16cg(s0 + XB_H + dst, g_Wxh + row * D_ + ku * 8);
        cp16cg(s0 + XB_L + dst, g_Wxl + row * D_ + ku * 8);
    }
    CP_COMMIT();

    #pragma unroll
    for (int j = 0; j < 32; j++) {              // A: 8192 float4 units
        int u = tid + 256 * j;
        int row = u >> 7, f4 = u & 127;
        float4 xv = *(const float4*)(inputs + (size_t)(m0 + row) * D_ + f4 * 4);
        __nv_bfloat16 h0 = __float2bfloat16(xv.x), h1 = __float2bfloat16(xv.y);
        __nv_bfloat16 h2 = __float2bfloat16(xv.z), h3 = __float2bfloat16(xv.w);
        __nv_bfloat16 l0 = __float2bfloat16(xv.x - __bfloat162float(h0));
        __nv_bfloat16 l1 = __float2bfloat16(xv.y - __bfloat162float(h1));
        __nv_bfloat16 l2 = __float2bfloat16(xv.z - __bfloat162float(h2));
        __nv_bfloat16 l3 = __float2bfloat16(xv.w - __bfloat162float(h3));
        uint2 ph, pl;
        ph.x = ((uint32_t)__bfloat16_as_ushort(h1) << 16) | __bfloat16_as_ushort(h0);
        ph.y = ((uint32_t)__bfloat16_as_ushort(h3) << 16) | __bfloat16_as_ushort(h2);
        pl.x = ((uint32_t)__bfloat16_as_ushort(l1) << 16) | __bfloat16_as_ushort(l0);
        pl.y = ((uint32_t)__bfloat16_as_ushort(l3) << 16) | __bfloat16_as_ushort(l2);
        uint32_t off = (uint32_t)row * XROWB + (uint32_t)f4 * 8u;
        *(uint2*)(xsm + XA_H + off) = ph;
        *(uint2*)(xsm + XA_L + off) = pl;
    }
    cp_wait<0>();
    __syncthreads();

    int wm = (wid >> 1) * 16, nh = wid & 1;
    float acc[2][4];
    #pragma unroll
    for (int j = 0; j < 2; j++)
        #pragma unroll
        for (int r = 0; r < 4; r++) acc[j][r] = 0.f;

    uint32_t aOff = (uint32_t)(wm + (lane & 15)) * XROWB + (uint32_t)((lane >> 4) << 4);
    uint32_t bOff = (uint32_t)(nh * 16 + (lane & 15)) * XROWB + (uint32_t)((lane >> 4) << 4);

    #pragma unroll 4
    for (int k16 = 0; k16 < 32; k16++) {
        uint32_t kb = (uint32_t)k16 * 32u;
        uint32_t ah[4], al[4], bh[4], bl[4];
        ldm4(s0 + XA_H + aOff + kb, ah);
        ldm4(s0 + XA_L + aOff + kb, al);
        ldm4(s0 + XB_H + bOff + kb, bh);
        ldm4(s0 + XB_L + bOff + kb, bl);
        #pragma unroll
        for (int j = 0; j < 2; j++) {
            mma_bf16(acc[j], ah, bh[j], bh[2 + j]);
            mma_bf16(acc[j], ah, bl[j], bl[2 + j]);
            mma_bf16(acc[j], al, bh[j], bh[2 + j]);
        }
    }

    int r0 = m0 + wm + (lane >> 2);
    #pragma unroll
    for (int j = 0; j < 2; j++) {
        int col = (nh * 2 + j) * 8 + (lane & 3) * 2;
        float b0 = g_bx[col], b1 = g_bx[col + 1];
        *(float2*)(g_Xproj + (size_t)r0 * 32 + col)       = make_float2(acc[j][0] + b0, acc[j][1] + b1);
        *(float2*)(g_Xproj + (size_t)(r0 + 8) * 32 + col) = make_float2(acc[j][2] + b0, acc[j][3] + b1);
    }
}

// ---------------- the persistent recurrence kernel ----------------
// smem: B resident fp16; A 4 chunks of K=128 (row stride 272B); resident tables.
#define BROWB 1040u
#define PB    0u
#define PA    66560u
#define PABUF 17408u
#define AROWB 272u
#define PW1S  140288u
#define WHS   156672u
#define PB1S  164864u
#define PB2S  166912u
#define CS    167168u
#define HSOFF 171264u
#define SMEM_DYN 175360
#define EPAD 68

__global__ __launch_bounds__(256, 1) void qlstm_kernel(
    const float* __restrict__ pW1, const float* __restrict__ pb1,
    const float* __restrict__ pb2, float* __restrict__ out)
{
    extern __shared__ __align__(16) char dsm[];
    const unsigned FULL = 0xffffffffu;
    uint32_t s0 = smem_u32(dsm);
    int tid = threadIdx.x, wid = tid >> 5, lane = tid & 31;
    int bid = blockIdx.x;
    int nt = bid & 7, mt = bid >> 3;
    int grp = mt;
    int n0 = nt * 64, m0 = mt * 64;

    int sidx = bid * 8 + wid;
    int qb = sidx >> 2, qg = sidx & 3;

    // ---- stage resident smem (one-time) ----
    #pragma unroll
    for (int j = 0; j < 16; j++) {              // B tile (single fp16)
        int u = tid + 256 * j;
        int row = u >> 6, ku = u & 63;
        cp16cg(s0 + PB + (uint32_t)row * BROWB + (uint32_t)ku * 16u,
               g_Bf + (size_t)(n0 + row) * H_ + ku * 8);
    }
    #pragma unroll
    for (int j = 0; j < 4; j++) {               // pW1 (16KB)
        int u = tid + 256 * j;
        cp16cg(s0 + PW1S + (uint32_t)u * 16u, pW1 + u * 4);
    }
    #pragma unroll
    for (int j = 0; j < 2; j++) {               // Wh tile (8KB)
        int u = tid + 256 * j;
        cp16cg(s0 + WHS + (uint32_t)u * 16u, g_Wh2t + (size_t)n0 * 32 + u * 4);
    }
    if (tid < 128) cp16cg(s0 + PB1S + (uint32_t)tid * 16u, pb1 + tid * 4);
    if (tid < 16)  cp16cg(s0 + PB2S + (uint32_t)tid * 16u, pb2 + n0 + tid * 4);
    CP_COMMIT();

    float* cs = (float*)(dsm + CS);
    #pragma unroll
    for (int j = 0; j < 4; j++) cs[tid + 256 * j] = 0.f;
    __stcg(g_Zpart + bid * 512 + tid, 0.f);
    __stcg(g_Zpart + bid * 512 + 256 + tid, 0.f);
    cp_wait<0>();
    groupbar(grp);

    // ---- hoisted constants ----
    const __half* Af = g_H1f + (size_t)m0 * H_;
    int wm = (wid >> 1) * 16, wn = (wid & 1) * 32;
    uint32_t aOff = (uint32_t)(wm + (lane & 15)) * AROWB + (uint32_t)((lane >> 4) << 4);
    uint32_t bOff = (uint32_t)(wn + (lane & 15)) * BROWB + (uint32_t)((lane >> 4) << 4);
    int arow[4], aun[4];
    uint32_t adst[4];
    #pragma unroll
    for (int j = 0; j < 4; j++) {
        int u = tid + 256 * j;
        arow[j] = u >> 4; aun[j] = u & 15;
        adst[j] = (uint32_t)arow[j] * AROWB + (uint32_t)aun[j] * 16u;
    }

    const float2* ryp = g_ry + qg * 16;
    const float2* prp = g_pr2 + qg * 16;
    const float* pw1s = (const float*)(dsm + PW1S);
    const float* pb1s = (const float*)(dsm + PB1S);
    const float* pb2s = (const float*)(dsm + PB2S);
    const float* whs  = (const float*)(dsm + WHS);

    for (int t = 0; t < T_; t++) {
        // ================= Q phase =================
        {
            float a = 0.f;
            if (lane < 8) {
                float xp = g_Xproj[((t * B_ + qb) * 4 + qg) * 8 + lane];
                float zacc = 0.f;
                const float* zp = g_Zpart + qb * 256 + qg * 8 + lane;
                #pragma unroll
                for (int p = 0; p < 8; p++) zacc += __ldcg(zp + p * 32);
                a = zacc + xp;
            }
            float sv, cv;
            __sincosf(a * 0.5f, &sv, &cv);

            float re[8], im[8];
            #pragma unroll
            for (int r = 0; r < 8; r++) { re[r] = 0.f; im[r] = 0.f; }
            if (lane == 0) re[0] = 1.f;

            #pragma unroll
            for (int q = 0; q < 5; q++) {
                int d = 16 >> q;
                float c = __shfl_sync(FULL, cv, q);
                float s = __shfl_sync(FULL, sv, q);
                #pragma unroll
                for (int r = 0; r < 8; r++) {
                    float pr = __shfl_xor_sync(FULL, re[r], d);
                    float pi = __shfl_xor_sync(FULL, im[r], d);
                    re[r] = c * re[r] + s * pi;
                    im[r] = c * im[r] - s * pr;
                }
            }
            #pragma unroll
            for (int q = 5; q < 8; q++) {
                int str = 1 << (7 - q);
                float c = __shfl_sync(FULL, cv, q);
                float s = __shfl_sync(FULL, sv, q);
                #pragma unroll
                for (int a0 = 0; a0 < 8; a0++) {
                    if (a0 & str) continue;
                    int b0 = a0 | str;
                    float tr0 = re[a0], ti0 = im[a0], tr1 = re[b0], ti1 = im[b0];
                    re[a0] = c * tr0 + s * ti1;
                    im[a0] = c * ti0 - s * tr1;
                    re[b0] = c * tr1 + s * ti0;
                    im[b0] = c * ti1 - s * tr0;
                }
            }

            #pragma unroll
            for (int l = 0; l < 2; l++) {
                #pragma unroll
                for (int q = 0; q < 5; q++) {
                    float2 ys = ryp[l * 8 + q];
                    int d = 16 >> q;
                    int hi = (lane >> (4 - q)) & 1;
                    float sgn = hi ? ys.y : -ys.y;
                    #pragma unroll
                    for (int r = 0; r < 8; r++) {
                        float pr = __shfl_xor_sync(FULL, re[r], d);
                        float pi = __shfl_xor_sync(FULL, im[r], d);
                        re[r] = ys.x * re[r] + sgn * pr;
                        im[r] = ys.x * im[r] + sgn * pi;
                    }
                }
                #pragma unroll
                for (int q = 5; q < 8; q++) {
                    float2 ys = ryp[l * 8 + q];
                    int str = 1 << (7 - q);
                    #pragma unroll
                    for (int a0 = 0; a0 < 8; a0++) {
                        if (a0 & str) continue;
                        int b0 = a0 | str;
                        float tr0 = re[a0], ti0 = im[a0], tr1 = re[b0], ti1 = im[b0];
                        re[a0] = ys.x * tr0 - ys.y * tr1;
                        im[a0] = ys.x * ti0 - ys.y * ti1;
                        re[b0] = ys.y * tr0 + ys.x * tr1;
                        im[b0] = ys.y * ti0 + ys.x * ti1;
                    }
                }
                if (l == 0) {
                    float2 pl = g_pl2[(qg * 2 + l) * 32 + lane];
                    #pragma unroll
                    for (int r = 0; r < 8; r++) {
                        float nr = pl.x * re[r] - pl.y * im[r];
                        im[r] = pl.x * im[r] + pl.y * re[r];
                        re[r] = nr;
                    }
                    #pragma unroll
                    for (int r = 0; r < 8; r++) {
                        float2 pq = prp[l * 8 + r];
                        float nr = pq.x * re[r] - pq.y * im[r];
                        im[r] = pq.x * im[r] + pq.y * re[r];
                        re[r] = nr;
                    }
                }
                #pragma unroll
                for (int ct = 0; ct < 4; ct++) {
                    int d = 8 >> ct, cb = 4 - ct;
                    int cbit = (lane >> cb) & 1;
                    #pragma unroll
                    for (int r = 0; r < 8; r++) {
                        float pr = __shfl_xor_sync(FULL, re[r], d);
                        float pi = __shfl_xor_sync(FULL, im[r], d);
                        re[r] = cbit ? pr : re[r];
                        im[r] = cbit ? pi : im[r];
                    }
                }
                {
                    int cbit = lane & 1;
                    #pragma unroll
                    for (int r = 0; r < 4; r++) {
                        float t1 = re[r], t2 = re[r + 4];
                        re[r]     = cbit ? t2 : t1;
                        re[r + 4] = cbit ? t1 : t2;
                        t1 = im[r]; t2 = im[r + 4];
                        im[r]     = cbit ? t2 : t1;
                        im[r + 4] = cbit ? t1 : t2;
                    }
                }
                {
                    float tt;
                    tt = re[4]; re[4] = re[6]; re[6] = tt;
                    tt = re[5]; re[5] = re[7]; re[7] = tt;
                    tt = im[4]; im[4] = im[6]; im[6] = tt;
                    tt = im[5]; im[5] = im[7]; im[7] = tt;
                }
                {
                    float tt;
                    tt = re[2]; re[2] = re[3]; re[3] = tt;
                    tt = re[6]; re[6] = re[7]; re[7] = tt;
                    tt = im[2]; im[2] = im[3]; im[3] = tt;
                    tt = im[6]; im[6] = im[7]; im[7] = tt;
                }
            }

            float p0 = re[0]*re[0]+im[0]*im[0], p1 = re[1]*re[1]+im[1]*im[1];
            float p2 = re[2]*re[2]+im[2]*im[2], p3 = re[3]*re[3]+im[3]*im[3];
            float p4 = re[4]*re[4]+im[4]*im[4], p5 = re[5]*re[5]+im[5]*im[5];
            float p6 = re[6]*re[6]+im[6]*im[6], p7 = re[7]*re[7]+im[7]*im[7];
            float S = p0+p1+p2+p3+p4+p5+p6+p7;
            float z[8];
            #pragma unroll
            for (int q = 0; q < 5; q++)
                z[q] = ((lane >> (4 - q)) & 1) ? -S : S;
            z[5] = (p0+p1+p2+p3) - (p4+p5+p6+p7);
            z[6] = (p0+p1+p4+p5) - (p2+p3+p6+p7);
            z[7] = (p0+p2+p4+p6) - (p1+p3+p5+p7);
            #pragma unroll
            for (int q = 0; q < 8; q++) {
                #pragma unroll
                for (int o = 16; o; o >>= 1) z[q] += __shfl_xor_sync(FULL, z[q], o);
            }

            // H1 = relu(z @ pW1 + pb1), vectorized half2 stores
            int row = qb * 4 + qg;
            #pragma unroll
            for (int j = 0; j < 8; j++) {
                int col = j * 64 + lane * 2;
                float2 bb = *(const float2*)(pb1s + col);
                float a0 = bb.x, a1 = bb.y;
                #pragma unroll
                for (int q = 0; q < 8; q++) {
                    float2 wv = *(const float2*)(pw1s + q * H_ + col);
                    a0 += z[q] * wv.x;
                    a1 += z[q] * wv.y;
                }
                a0 = fmaxf(a0, 0.f); a1 = fmaxf(a1, 0.f);
                *(__half2*)(g_H1f + row * H_ + col) = __floats2half2_rn(a0, a1);
            }
        }
        groupbar(grp);

        // ================= G phase: GEMM + LSTM + h-projection =================
        {
            float* outt = out + (size_t)t * (B_ * H_);
            #pragma unroll
            for (int c = 0; c < 4; c++) {
                uint32_t sb = s0 + PA + c * PABUF;
                int kb = c * 128;
                #pragma unroll
                for (int j = 0; j < 4; j++)
                    cp16cg(sb + adst[j], Af + (size_t)arow[j] * H_ + kb + aun[j] * 8);
                CP_COMMIT();
            }
            float acc[4][4];
            #pragma unroll
            for (int j = 0; j < 4; j++)
                #pragma unroll
                for (int r = 0; r < 4; r++) acc[j][r] = 0.f;

            #define GSTEP(CC, NW) { \
                cp_wait<NW>(); \
                __syncthreads(); \
                uint32_t abuf = s0 + PA + (CC) * PABUF; \
                uint32_t bko = (uint32_t)(CC) * 256u; \
                _Pragma("unroll") \
                for (int kk = 0; kk < 8; kk++) { \
                    uint32_t kb2 = kk * 32; \
                    uint32_t af[4], bf2[2][4]; \
                    ldm4(abuf + aOff + kb2, af); \
                    ldm4(s0 + PB + bOff + bko + kb2, bf2[0]); \
                    ldm4(s0 + PB + bOff + 16 * BROWB + bko + kb2, bf2[1]); \
                    _Pragma("unroll") \
                    for (int j = 0; j < 4; j++) { \
                        int p = j >> 1, sb2 = j & 1; \
                        mma_f16(acc[j], af, bf2[p][sb2], bf2[p][2 + sb2]); \
                    } \
                } }
            GSTEP(0, 3) GSTEP(1, 2) GSTEP(2, 1) GSTEP(3, 0)
            #undef GSTEP
            __syncthreads();

            float* sp = (float*)(dsm + PA);
            int r0 = wm + (lane >> 2);
            #pragma unroll
            for (int j = 0; j < 4; j++) {
                int cc = wn + j * 8 + (lane & 3) * 2;
                sp[r0 * EPAD + cc]           = acc[j][0];
                sp[r0 * EPAD + cc + 1]       = acc[j][1];
                sp[(r0 + 8) * EPAD + cc]     = acc[j][2];
                sp[(r0 + 8) * EPAD + cc + 1] = acc[j][3];
            }
            __syncthreads();

            float* hs = (float*)(dsm + HSOFF);
            bool last = (t == T_ - 1);
            #pragma unroll
            for (int jj = 0; jj < 4; jj++) {
                int e = tid + 256 * jj;
                int bi = e >> 6, col = e & 63;
                float bias = pb2s[col];
                float fv = fsigmoid(sp[(bi * 4 + 0) * EPAD + col] + bias);
                float iv = fsigmoid(sp[(bi * 4 + 1) * EPAD + col] + bias);
                float uv = ftanh   (sp[(bi * 4 + 2) * EPAD + col] + bias);
                float ov = fsigmoid(sp[(bi * 4 + 3) * EPAD + col] + bias);
                float cc2 = fv * cs[e] + iv * uv;
                float hh2 = ov * ftanh(cc2);
                cs[e] = cc2;
                int batch = mt * 16 + bi;
                int idx = batch * H_ + n0 + col;
                outt[idx] = hh2;
                hs[bi * 64 + col] = hh2;
                if (last) {
                    out[(size_t)T_ * B_ * H_ + idx] = hh2;
                    out[(size_t)T_ * B_ * H_ + B_ * H_ + idx] = cc2;
                }
            }
            __syncthreads();

            #pragma unroll
            for (int jj = 0; jj < 2; jj++) {
                int idx2 = tid + 256 * jj;
                int bi = idx2 >> 5, o = idx2 & 31;
                const float* hh = hs + bi * 64;
                const float* wr = whs + o;
                float sacc = 0.f;
                #pragma unroll 16
                for (int c2 = 0; c2 < 64; c2++) sacc += hh[c2] * wr[c2 * 32];
                __stcg(g_Zpart + (mt * 16 + bi) * 256 + nt * 32 + o, sacc);
            }
        }
        if (t < T_ - 1) groupbar(grp);
    }
}

// ---------------- host ----------------
extern "C" void kernel_launch(void* const* d_in, const int* in_sizes, int n_in,
                              void* d_out, int out_size) {
    const float* inputs = (const float*)d_in[0];
    const float* qpf = (const float*)d_in[1];
    const float* qpi = (const float*)d_in[2];
    const float* qpu = (const float*)d_in[3];
    const float* qpo = (const float*)d_in[4];
    const float* Wf  = (const float*)d_in[5];
    const float* bf  = (const float*)d_in[6];
    const float* Wi  = (const float*)d_in[7];
    const float* bi  = (const float*)d_in[8];
    const float* Wu  = (const float*)d_in[9];
    const float* bu  = (const float*)d_in[10];
    const float* Wo  = (const float*)d_in[11];
    const float* bo  = (const float*)d_in[12];
    const float* pW1 = (const float*)d_in[13];
    const float* pb1 = (const float*)d_in[14];
    const float* pW2 = (const float*)d_in[15];
    const float* pb2 = (const float*)d_in[16];
    float* out = (float*)d_out;

    cudaFuncSetAttribute(qlstm_kernel, cudaFuncAttributeMaxDynamicSharedMemorySize, SMEM_DYN);
    cudaFuncSetAttribute(xproj_kernel, cudaFuncAttributeMaxDynamicSharedMemorySize, XP3_SMEM);

    prep_kernel<<<1089, 256>>>(pW2, Wf, Wi, Wu, Wo, bf, bi, bu, bo,
                               qpf, qpi, qpu, qpo);
    xproj_kernel<<<(T_ * B_) / 64, 256, XP3_SMEM>>>(inputs);
    qlstm_kernel<<<128, 256, SMEM_DYN>>>(pW1, pb1, pb2, out);
}

// round 17
// speedup vs baseline: 1.7514x; 1.0166x over previous
#include <cuda_runtime.h>
#include <cuda_bf16.h>
#include <cuda_fp16.h>
#include <math.h>
#include <stdint.h>

#define T_  64
#define B_  256
#define D_  512
#define H_  512

// ---------------- device scratch (allocation-free rule) ----------------
__device__ __half g_H1f[B_ * 4 * H_];          // fp16(H1), row = b*4 + gate
__device__ __half g_Bf[H_ * H_];               // fp16(pW2^T), [n][k]
__device__ __half g_Wxh[32 * D_];              // hi fp16(Wx^T) [o][k] for xproj
__device__ __half g_Wxl[32 * D_];              // lo fp16(Wx^T)
__device__ __half g_pW1h[8 * H_];              // fp16(pW1)
__device__ float g_bx[32];                     // gate bias vector
__device__ float g_Xproj[T_ * B_ * 32];        // x_t @ W + b, [t*B+b][g*8+q]
__device__ float g_Zpart[B_ * 256];            // [batch][p][32] partial h-projections
__device__ float g_Wh2t[H_ * 32];              // W[D+col][g*8+q] as [col][32]
__device__ float2 g_ry[4 * 2 * 8];             // (cy,sy) per (g,l,q)
__device__ float2 g_pl2[4 * 2 * 32];           // lane-deferred RZ phase per (g,l,lane)
__device__ float2 g_pr2[4 * 2 * 8];            // reg-deferred RZ phase per (g,l,r)
__device__ int g_gcnt[16 * 32];                // padded: one 128B line per group
__device__ volatile int g_ggen[16 * 32];

// ---------------- PTX helpers ----------------
__device__ __forceinline__ uint32_t smem_u32(const void* p) {
    uint32_t a;
    asm("{ .reg .u64 t; cvta.to.shared.u64 t, %1; cvt.u32.u64 %0, t; }" : "=r"(a) : "l"(p));
    return a;
}
__device__ __forceinline__ void cp16cg(uint32_t dst, const void* src) {
    asm volatile("cp.async.cg.shared.global [%0], [%1], 16;" :: "r"(dst), "l"(src) : "memory");
}
#define CP_COMMIT() asm volatile("cp.async.commit_group;" ::: "memory")
template<int N> __device__ __forceinline__ void cp_wait() {
    asm volatile("cp.async.wait_group %0;" :: "n"(N) : "memory");
}
__device__ __forceinline__ void ldm4(uint32_t addr, uint32_t* r) {
    asm volatile("ldmatrix.sync.aligned.m8n8.x4.shared.b16 {%0,%1,%2,%3}, [%4];"
        : "=r"(r[0]), "=r"(r[1]), "=r"(r[2]), "=r"(r[3]) : "r"(addr));
}
__device__ __forceinline__ void mma_f16(float* c, const uint32_t* a, uint32_t b0, uint32_t b1) {
    asm volatile(
        "mma.sync.aligned.m16n8k16.row.col.f32.f16.f16.f32 "
        "{%0,%1,%2,%3}, {%4,%5,%6,%7}, {%8,%9}, {%0,%1,%2,%3};"
        : "+f"(c[0]), "+f"(c[1]), "+f"(c[2]), "+f"(c[3])
        : "r"(a[0]), "r"(a[1]), "r"(a[2]), "r"(a[3]), "r"(b0), "r"(b1));
}
// fast activations: __expf + fast divide (~1e-6 rel err, well under budget)
__device__ __forceinline__ float fsigmoid(float x) {
    return __fdividef(1.f, 1.f + __expf(-x));
}
__device__ __forceinline__ float ftanh(float x) {
    x = fminf(fmaxf(x, -15.f), 15.f);
    float e = __expf(2.f * x);
    return 1.f - __fdividef(2.f, e + 1.f);
}

// ---------------- group barrier: 8 blocks (one m-tile group), padded lines ---
__device__ __forceinline__ void groupbar(int grp) {
    __syncthreads();
    if (threadIdx.x == 0) {
        __threadfence();
        int gen = g_ggen[grp * 32];
        if (atomicAdd(&g_gcnt[grp * 32], 1) == 7) {
            g_gcnt[grp * 32] = 0;
            __threadfence();
            g_ggen[grp * 32] = gen + 1;
        } else {
            while (g_ggen[grp * 32] == gen) { }
        }
    }
    __syncthreads();
}

// ---------------- merged prep kernel ----------------
// blocks [0,1024): bprep; [1024,1088): whprep; 1088: trig; [1089,1105): pW1 fp16
__global__ void prep_kernel(
    const float* __restrict__ pW2, const float* __restrict__ pW1,
    const float* __restrict__ Wf, const float* __restrict__ Wi,
    const float* __restrict__ Wu, const float* __restrict__ Wo,
    const float* __restrict__ bf, const float* __restrict__ bi,
    const float* __restrict__ bu, const float* __restrict__ bo,
    const float* __restrict__ qpf, const float* __restrict__ qpi,
    const float* __restrict__ qpu, const float* __restrict__ qpo)
{
    int blk = blockIdx.x, tid = threadIdx.x;
    if (blk < 1024) {
        int i = blk * 256 + tid;
        int n = i >> 9, k = i & 511;
        g_Bf[i] = __float2half(pW2[k * H_ + n]);
        return;
    }
    if (blk < 1088) {
        int i = (blk - 1024) * 256 + tid;    // 0..16383
        {
            int col = i >> 5, o = i & 31, g = o >> 3, q = o & 7;
            const float* W = (g == 0) ? Wf : (g == 1) ? Wi : (g == 2) ? Wu : Wo;
            g_Wh2t[i] = W[(D_ + col) * 8 + q];
        }
        {
            int o = i >> 9, k = i & 511, g = o >> 3, q = o & 7;
            const float* W = (g == 0) ? Wf : (g == 1) ? Wi : (g == 2) ? Wu : Wo;
            float v = W[k * 8 + q];
            __half hi = __float2half(v);
            __half lo = __float2half(v - __half2float(hi));
            g_Wxh[i] = hi; g_Wxl[i] = lo;
        }
        if (i < 32) {
            int g = i >> 3, q = i & 7;
            const float* bb = (g == 0) ? bf : (g == 1) ? bi : (g == 2) ? bu : bo;
            g_bx[i] = bb[q];
        }
        return;
    }
    if (blk >= 1089) {
        int i = (blk - 1089) * 256 + tid;    // 0..4095
        g_pW1h[i] = __float2half(pW1[i]);
        return;
    }
    // trig tables (block 1088, 256 threads)
    int i = tid;
    const float* qps[4] = {qpf, qpi, qpu, qpo};
    if (i < 64) {
        int g = i >> 4, l = (i >> 3) & 1, q = i & 7;
        const float* qp = qps[g];
        float th = qp[(l * 8 + q) * 3 + 0] * 0.5f;
        g_ry[i] = make_float2(cosf(th), sinf(th));
        int r = q;
        float prr = 1.f, pri = 0.f;
        #pragma unroll
        for (int qq = 5; qq < 8; qq++) {
            float tz = qp[(l * 8 + qq) * 3 + 1] * 0.5f;
            float cz = cosf(tz), sz = sinf(tz);
            float zn = ((r >> (7 - qq)) & 1) ? sz : -sz;
            float nr = prr * cz - pri * zn;
            float ni = prr * zn + pri * cz;
            prr = nr; pri = ni;
        }
        g_pr2[i] = make_float2(prr, pri);
    }
    {
        int g = i >> 6, l = (i >> 5) & 1, ln = i & 31;
        const float* qp = qps[g];
        float prr = 1.f, pri = 0.f;
        #pragma unroll
        for (int q = 0; q < 5; q++) {
            float tz = qp[(l * 8 + q) * 3 + 1] * 0.5f;
            float cz = cosf(tz), sz = sinf(tz);
            float zn = ((ln >> (4 - q)) & 1) ? sz : -sz;
            float nr = prr * cz - pri * zn;
            float ni = prr * zn + pri * cz;
            prr = nr; pri = ni;
        }
        g_pl2[i] = make_float2(prr, pri);
    }
}

// ---------------- xproj v5: 2-term fp16 HMMA GEMM, 256 threads --------------
#define XROWB 1040u
#define XA   0u
#define XB_H 66560u
#define XB_L 133120u
#define XP3_SMEM 199680

__global__ __launch_bounds__(256, 1) void xproj_kernel(const float* __restrict__ inputs)
{
    extern __shared__ __align__(16) char xsm[];
    uint32_t s0 = smem_u32(xsm);
    int tid = threadIdx.x, wid = tid >> 5, lane = tid & 31;
    int m0 = blockIdx.x * 64;

    #pragma unroll
    for (int j = 0; j < 8; j++) {               // B: 2048 16B units
        int u = tid + 256 * j;
        int row = u >> 6, ku = u & 63;
        uint32_t dst = (uint32_t)row * XROWB + (uint32_t)ku * 16u;
        cp16cg(s0 + XB_H + dst, g_Wxh + row * D_ + ku * 8);
        cp16cg(s0 + XB_L + dst, g_Wxl + row * D_ + ku * 8);
    }
    CP_COMMIT();

    #pragma unroll
    for (int j = 0; j < 32; j++) {              // A: fp32 -> single fp16
        int u = tid + 256 * j;
        int row = u >> 7, f4 = u & 127;
        float4 xv = *(const float4*)(inputs + (size_t)(m0 + row) * D_ + f4 * 4);
        __half2 p0 = __floats2half2_rn(xv.x, xv.y);
        __half2 p1 = __floats2half2_rn(xv.z, xv.w);
        uint32_t off = (uint32_t)row * XROWB + (uint32_t)f4 * 8u;
        *(__half2*)(xsm + XA + off)     = p0;
        *(__half2*)(xsm + XA + off + 4) = p1;
    }
    cp_wait<0>();
    __syncthreads();

    int wm = (wid >> 1) * 16, nh = wid & 1;
    float acc[2][4];
    #pragma unroll
    for (int j = 0; j < 2; j++)
        #pragma unroll
        for (int r = 0; r < 4; r++) acc[j][r] = 0.f;

    uint32_t aOff = (uint32_t)(wm + (lane & 15)) * XROWB + (uint32_t)((lane >> 4) << 4);
    uint32_t bOff = (uint32_t)(nh * 16 + (lane & 15)) * XROWB + (uint32_t)((lane >> 4) << 4);

    #pragma unroll 4
    for (int k16 = 0; k16 < 32; k16++) {
        uint32_t kb = (uint32_t)k16 * 32u;
        uint32_t av[4], bh[4], bl[4];
        ldm4(s0 + XA + aOff + kb, av);
        ldm4(s0 + XB_H + bOff + kb, bh);
        ldm4(s0 + XB_L + bOff + kb, bl);
        #pragma unroll
        for (int j = 0; j < 2; j++) {
            mma_f16(acc[j], av, bh[j], bh[2 + j]);
            mma_f16(acc[j], av, bl[j], bl[2 + j]);
        }
    }

    int r0 = m0 + wm + (lane >> 2);
    #pragma unroll
    for (int j = 0; j < 2; j++) {
        int col = (nh * 2 + j) * 8 + (lane & 3) * 2;
        float b0 = g_bx[col], b1 = g_bx[col + 1];
        *(float2*)(g_Xproj + (size_t)r0 * 32 + col)       = make_float2(acc[j][0] + b0, acc[j][1] + b1);
        *(float2*)(g_Xproj + (size_t)(r0 + 8) * 32 + col) = make_float2(acc[j][2] + b0, acc[j][3] + b1);
    }
}

// ---------------- the persistent recurrence kernel ----------------
// smem: B resident fp16; A 4 chunks of K=128 (row stride 272B); resident tables.
#define BROWB 1040u
#define PB    0u
#define PA    66560u
#define PABUF 17408u
#define AROWB 272u
#define PW1S  140288u
#define WHS   156672u
#define PB1S  164864u
#define PB2S  166912u
#define CS    167168u
#define HSOFF 171264u
#define SMEM_DYN 175360
#define EPAD 68

__global__ __launch_bounds__(256, 1) void qlstm_kernel(
    const float* __restrict__ pb1, const float* __restrict__ pb2,
    float* __restrict__ out)
{
    extern __shared__ __align__(16) char dsm[];
    const unsigned FULL = 0xffffffffu;
    uint32_t s0 = smem_u32(dsm);
    int tid = threadIdx.x, wid = tid >> 5, lane = tid & 31;
    int bid = blockIdx.x;
    int nt = bid & 7, mt = bid >> 3;
    int grp = mt;
    int n0 = nt * 64, m0 = mt * 64;

    int sidx = bid * 8 + wid;
    int qb = sidx >> 2, qg = sidx & 3;

    // ---- stage resident smem (one-time) ----
    #pragma unroll
    for (int j = 0; j < 16; j++) {              // B tile (single fp16)
        int u = tid + 256 * j;
        int row = u >> 6, ku = u & 63;
        cp16cg(s0 + PB + (uint32_t)row * BROWB + (uint32_t)ku * 16u,
               g_Bf + (size_t)(n0 + row) * H_ + ku * 8);
    }
    #pragma unroll
    for (int j = 0; j < 2; j++) {               // pW1 fp16 (8KB, 512 units)
        int u = tid + 256 * j;
        cp16cg(s0 + PW1S + (uint32_t)u * 16u, g_pW1h + u * 8);
    }
    #pragma unroll
    for (int j = 0; j < 2; j++) {               // Wh tile (8KB)
        int u = tid + 256 * j;
        cp16cg(s0 + WHS + (uint32_t)u * 16u, g_Wh2t + (size_t)n0 * 32 + u * 4);
    }
    if (tid < 128) cp16cg(s0 + PB1S + (uint32_t)tid * 16u, pb1 + tid * 4);
    if (tid < 16)  cp16cg(s0 + PB2S + (uint32_t)tid * 16u, pb2 + n0 + tid * 4);
    CP_COMMIT();

    float* cs = (float*)(dsm + CS);
    #pragma unroll
    for (int j = 0; j < 4; j++) cs[tid + 256 * j] = 0.f;
    __stcg(g_Zpart + bid * 512 + tid, 0.f);
    __stcg(g_Zpart + bid * 512 + 256 + tid, 0.f);
    cp_wait<0>();
    groupbar(grp);

    // ---- hoisted constants ----
    const __half* Af = g_H1f + (size_t)m0 * H_;
    int wm = (wid >> 1) * 16, wn = (wid & 1) * 32;
    uint32_t aOff = (uint32_t)(wm + (lane & 15)) * AROWB + (uint32_t)((lane >> 4) << 4);
    uint32_t bOff = (uint32_t)(wn + (lane & 15)) * BROWB + (uint32_t)((lane >> 4) << 4);
    int arow[4], aun[4];
    uint32_t adst[4];
    #pragma unroll
    for (int j = 0; j < 4; j++) {
        int u = tid + 256 * j;
        arow[j] = u >> 4; aun[j] = u & 15;
        adst[j] = (uint32_t)arow[j] * AROWB + (uint32_t)aun[j] * 16u;
    }

    const float2* ryp = g_ry + qg * 16;
    const float2* prp = g_pr2 + qg * 16;
    const __half2* pw1h = (const __half2*)(dsm + PW1S);
    const float* pb1s = (const float*)(dsm + PB1S);
    const float* pb2s = (const float*)(dsm + PB2S);
    const float* whs  = (const float*)(dsm + WHS);

    for (int t = 0; t < T_; t++) {
        // ================= Q phase =================
        {
            float a = 0.f;
            if (lane < 8) {
                float xp = g_Xproj[((t * B_ + qb) * 4 + qg) * 8 + lane];
                float zacc = 0.f;
                const float* zp = g_Zpart + qb * 256 + qg * 8 + lane;
                #pragma unroll
                for (int p = 0; p < 8; p++) zacc += __ldcg(zp + p * 32);
                a = zacc + xp;
            }
            float sv, cv;
            __sincosf(a * 0.5f, &sv, &cv);

            float re[8], im[8];
            #pragma unroll
            for (int r = 0; r < 8; r++) { re[r] = 0.f; im[r] = 0.f; }
            if (lane == 0) re[0] = 1.f;

            #pragma unroll
            for (int q = 0; q < 5; q++) {
                int d = 16 >> q;
                float c = __shfl_sync(FULL, cv, q);
                float s = __shfl_sync(FULL, sv, q);
                #pragma unroll
                for (int r = 0; r < 8; r++) {
                    float pr = __shfl_xor_sync(FULL, re[r], d);
                    float pi = __shfl_xor_sync(FULL, im[r], d);
                    re[r] = c * re[r] + s * pi;
                    im[r] = c * im[r] - s * pr;
                }
            }
            #pragma unroll
            for (int q = 5; q < 8; q++) {
                int str = 1 << (7 - q);
                float c = __shfl_sync(FULL, cv, q);
                float s = __shfl_sync(FULL, sv, q);
                #pragma unroll
                for (int a0 = 0; a0 < 8; a0++) {
                    if (a0 & str) continue;
                    int b0 = a0 | str;
                    float tr0 = re[a0], ti0 = im[a0], tr1 = re[b0], ti1 = im[b0];
                    re[a0] = c * tr0 + s * ti1;
                    im[a0] = c * ti0 - s * tr1;
                    re[b0] = c * tr1 + s * ti0;
                    im[b0] = c * ti1 - s * tr0;
                }
            }

            #pragma unroll
            for (int l = 0; l < 2; l++) {
                #pragma unroll
                for (int q = 0; q < 5; q++) {
                    float2 ys = ryp[l * 8 + q];
                    int d = 16 >> q;
                    int hi = (lane >> (4 - q)) & 1;
                    float sgn = hi ? ys.y : -ys.y;
                    #pragma unroll
                    for (int r = 0; r < 8; r++) {
                        float pr = __shfl_xor_sync(FULL, re[r], d);
                        float pi = __shfl_xor_sync(FULL, im[r], d);
                        re[r] = ys.x * re[r] + sgn * pr;
                        im[r] = ys.x * im[r] + sgn * pi;
                    }
                }
                #pragma unroll
                for (int q = 5; q < 8; q++) {
                    float2 ys = ryp[l * 8 + q];
                    int str = 1 << (7 - q);
                    #pragma unroll
                    for (int a0 = 0; a0 < 8; a0++) {
                        if (a0 & str) continue;
                        int b0 = a0 | str;
                        float tr0 = re[a0], ti0 = im[a0], tr1 = re[b0], ti1 = im[b0];
                        re[a0] = ys.x * tr0 - ys.y * tr1;
                        im[a0] = ys.x * ti0 - ys.y * ti1;
                        re[b0] = ys.y * tr0 + ys.x * tr1;
                        im[b0] = ys.y * ti0 + ys.x * ti1;
                    }
                }
                if (l == 0) {
                    float2 pl = g_pl2[(qg * 2 + l) * 32 + lane];
                    #pragma unroll
                    for (int r = 0; r < 8; r++) {
                        float nr = pl.x * re[r] - pl.y * im[r];
                        im[r] = pl.x * im[r] + pl.y * re[r];
                        re[r] = nr;
                    }
                    #pragma unroll
                    for (int r = 0; r < 8; r++) {
                        float2 pq = prp[l * 8 + r];
                        float nr = pq.x * re[r] - pq.y * im[r];
                        im[r] = pq.x * im[r] + pq.y * re[r];
                        re[r] = nr;
                    }
                }
                #pragma unroll
                for (int ct = 0; ct < 4; ct++) {
                    int d = 8 >> ct, cb = 4 - ct;
                    int cbit = (lane >> cb) & 1;
                    #pragma unroll
                    for (int r = 0; r < 8; r++) {
                        float pr = __shfl_xor_sync(FULL, re[r], d);
                        float pi = __shfl_xor_sync(FULL, im[r], d);
                        re[r] = cbit ? pr : re[r];
                        im[r] = cbit ? pi : im[r];
                    }
                }
                {
                    int cbit = lane & 1;
                    #pragma unroll
                    for (int r = 0; r < 4; r++) {
                        float t1 = re[r], t2 = re[r + 4];
                        re[r]     = cbit ? t2 : t1;
                        re[r + 4] = cbit ? t1 : t2;
                        t1 = im[r]; t2 = im[r + 4];
                        im[r]     = cbit ? t2 : t1;
                        im[r + 4] = cbit ? t1 : t2;
                    }
                }
                {
                    float tt;
                    tt = re[4]; re[4] = re[6]; re[6] = tt;
                    tt = re[5]; re[5] = re[7]; re[7] = tt;
                    tt = im[4]; im[4] = im[6]; im[6] = tt;
                    tt = im[5]; im[5] = im[7]; im[7] = tt;
                }
                {
                    float tt;
                    tt = re[2]; re[2] = re[3]; re[3] = tt;
                    tt = re[6]; re[6] = re[7]; re[7] = tt;
                    tt = im[2]; im[2] = im[3]; im[3] = tt;
                    tt = im[6]; im[6] = im[7]; im[7] = tt;
                }
            }

            float p0 = re[0]*re[0]+im[0]*im[0], p1 = re[1]*re[1]+im[1]*im[1];
            float p2 = re[2]*re[2]+im[2]*im[2], p3 = re[3]*re[3]+im[3]*im[3];
            float p4 = re[4]*re[4]+im[4]*im[4], p5 = re[5]*re[5]+im[5]*im[5];
            float p6 = re[6]*re[6]+im[6]*im[6], p7 = re[7]*re[7]+im[7]*im[7];
            float S = p0+p1+p2+p3+p4+p5+p6+p7;
            float z[8];
            #pragma unroll
            for (int q = 0; q < 5; q++)
                z[q] = ((lane >> (4 - q)) & 1) ? -S : S;
            z[5] = (p0+p1+p2+p3) - (p4+p5+p6+p7);
            z[6] = (p0+p1+p4+p5) - (p2+p3+p6+p7);
            z[7] = (p0+p2+p4+p6) - (p1+p3+p5+p7);
            #pragma unroll
            for (int q = 0; q < 8; q++) {
                #pragma unroll
                for (int o = 16; o; o >>= 1) z[q] += __shfl_xor_sync(FULL, z[q], o);
            }

            // H1 = relu(z @ pW1 + pb1), fp16 weights, fp32 accum, half2 stores
            int row = qb * 4 + qg;
            #pragma unroll
            for (int j = 0; j < 8; j++) {
                int col = j * 64 + lane * 2;
                float2 bb = *(const float2*)(pb1s + col);
                float a0 = bb.x, a1 = bb.y;
                #pragma unroll
                for (int q = 0; q < 8; q++) {
                    float2 wf = __half22float2(pw1h[(q * H_ + col) >> 1]);
                    a0 += z[q] * wf.x;
                    a1 += z[q] * wf.y;
                }
                a0 = fmaxf(a0, 0.f); a1 = fmaxf(a1, 0.f);
                *(__half2*)(g_H1f + row * H_ + col) = __floats2half2_rn(a0, a1);
            }
        }
        groupbar(grp);

        // ================= G phase: GEMM + LSTM + h-projection =================
        {
            float* outt = out + (size_t)t * (B_ * H_);
            #pragma unroll
            for (int c = 0; c < 4; c++) {
                uint32_t sb = s0 + PA + c * PABUF;
                int kb = c * 128;
                #pragma unroll
                for (int j = 0; j < 4; j++)
                    cp16cg(sb + adst[j], Af + (size_t)arow[j] * H_ + kb + aun[j] * 8);
                CP_COMMIT();
            }
            float acc[4][4];
            #pragma unroll
            for (int j = 0; j < 4; j++)
                #pragma unroll
                for (int r = 0; r < 4; r++) acc[j][r] = 0.f;

            #define GSTEP(CC, NW) { \
                cp_wait<NW>(); \
                __syncthreads(); \
                uint32_t abuf = s0 + PA + (CC) * PABUF; \
                uint32_t bko = (uint32_t)(CC) * 256u; \
                _Pragma("unroll") \
                for (int kk = 0; kk < 8; kk++) { \
                    uint32_t kb2 = kk * 32; \
                    uint32_t af[4], bf2[2][4]; \
                    ldm4(abuf + aOff + kb2, af); \
                    ldm4(s0 + PB + bOff + bko + kb2, bf2[0]); \
                    ldm4(s0 + PB + bOff + 16 * BROWB + bko + kb2, bf2[1]); \
                    _Pragma("unroll") \
                    for (int j = 0; j < 4; j++) { \
                        int p = j >> 1, sb2 = j & 1; \
                        mma_f16(acc[j], af, bf2[p][sb2], bf2[p][2 + sb2]); \
                    } \
                } }
            GSTEP(0, 3) GSTEP(1, 2) GSTEP(2, 1) GSTEP(3, 0)
            #undef GSTEP
            __syncthreads();

            float* sp = (float*)(dsm + PA);
            int r0 = wm + (lane >> 2);
            #pragma unroll
            for (int j = 0; j < 4; j++) {
                int cc = wn + j * 8 + (lane & 3) * 2;
                sp[r0 * EPAD + cc]           = acc[j][0];
                sp[r0 * EPAD + cc + 1]       = acc[j][1];
                sp[(r0 + 8) * EPAD + cc]     = acc[j][2];
                sp[(r0 + 8) * EPAD + cc + 1] = acc[j][3];
            }
            __syncthreads();

            float* hs = (float*)(dsm + HSOFF);
            bool last = (t == T_ - 1);
            #pragma unroll
            for (int jj = 0; jj < 4; jj++) {
                int e = tid + 256 * jj;
                int bi = e >> 6, col = e & 63;
                float bias = pb2s[col];
                float fv = fsigmoid(sp[(bi * 4 + 0) * EPAD + col] + bias);
                float iv = fsigmoid(sp[(bi * 4 + 1) * EPAD + col] + bias);
                float uv = ftanh   (sp[(bi * 4 + 2) * EPAD + col] + bias);
                float ov = fsigmoid(sp[(bi * 4 + 3) * EPAD + col] + bias);
                float cc2 = fv * cs[e] + iv * uv;
                float hh2 = ov * ftanh(cc2);
                cs[e] = cc2;
                int batch = mt * 16 + bi;
                int idx = batch * H_ + n0 + col;
                outt[idx] = hh2;
                hs[bi * 64 + col] = hh2;
                if (last) {
                    out[(size_t)T_ * B_ * H_ + idx] = hh2;
                    out[(size_t)T_ * B_ * H_ + B_ * H_ + idx] = cc2;
                }
            }
            __syncthreads();

            #pragma unroll
            for (int jj = 0; jj < 2; jj++) {
                int idx2 = tid + 256 * jj;
                int bi = idx2 >> 5, o = idx2 & 31;
                const float* hh = hs + bi * 64;
                const float* wr = whs + o;
                float sacc = 0.f;
                #pragma unroll 16
                for (int c2 = 0; c2 < 64; c2++) sacc += hh[c2] * wr[c2 * 32];
                __stcg(g_Zpart + (mt * 16 + bi) * 256 + nt * 32 + o, sacc);
            }
        }
        if (t < T_ - 1) groupbar(grp);
    }
}

// ---------------- host ----------------
extern "C" void kernel_launch(void* const* d_in, const int* in_sizes, int n_in,
                              void* d_out, int out_size) {
    const float* inputs = (const float*)d_in[0];
    const float* qpf = (const float*)d_in[1];
    const float* qpi = (const float*)d_in[2];
    const float* qpu = (const float*)d_in[3];
    const float* qpo = (const float*)d_in[4];
    const float* Wf  = (const float*)d_in[5];
    const float* bf  = (const float*)d_in[6];
    const float* Wi  = (const float*)d_in[7];
    const float* bi  = (const float*)d_in[8];
    const float* Wu  = (const float*)d_in[9];
    const float* bu  = (const float*)d_in[10];
    const float* Wo  = (const float*)d_in[11];
    const float* bo  = (const float*)d_in[12];
    const float* pW1 = (const float*)d_in[13];
    const float* pb1 = (const float*)d_in[14];
    const float* pW2 = (const float*)d_in[15];
    const float* pb2 = (const float*)d_in[16];
    float* out = (float*)d_out;

    cudaFuncSetAttribute(qlstm_kernel, cudaFuncAttributeMaxDynamicSharedMemorySize, SMEM_DYN);
    cudaFuncSetAttribute(xproj_kernel, cudaFuncAttributeMaxDynamicSharedMemorySize, XP3_SMEM);

    prep_kernel<<<1105, 256>>>(pW2, pW1, Wf, Wi, Wu, Wo, bf, bi, bu, bo,
                               qpf, qpi, qpu, qpo);
    xproj_kernel<<<(T_ * B_) / 64, 256, XP3_SMEM>>>(inputs);
    qlstm_kernel<<<128, 256, SMEM_DYN>>>(pb1, pb2, out);
}